// round 7
// baseline (speedup 1.0000x reference)
#include <cuda_runtime.h>
#include <cuda_bf16.h>
#include <cstdint>
#include <cstddef>

typedef __nv_bfloat16 bf16;

#define BATCH 4
#define SLEN  2048
#define DIN   1024
#define NTOK  (BATCH*SLEN)

// GEMM tile config: CTA 128x128x64, 4 warps (2x2), warp tile 64x64, 1 CTA/SM
#define BM 128
#define BN 128
#define BK 64
#define A_BYTES (128*128)
#define B_BYTES (128*128)
#define STAGE_BYTES (2*A_BYTES + 2*B_BYTES)   // 64KB
#define SM_A_HI 0
#define SM_A_LO (A_BYTES)
#define SM_B_HI (2*A_BYTES)
#define SM_B_LO (2*A_BYTES + B_BYTES)
#define SMEM_REQ (1024 + 2*STAGE_BYTES)       // ~129KB

// ---------------- scratch (device globals; no allocs allowed) ----------------
__device__ bf16 g_Xhi[(size_t)NTOK*DIN];
__device__ bf16 g_Xlo[(size_t)NTOK*DIN];
__device__ bf16 g_WThi[3][(size_t)DIN*DIN];   // W^T split; [0],[1] contiguous = QK merged B
__device__ bf16 g_WTlo[3][(size_t)DIN*DIN];
__device__ bf16 g_QKhi[(size_t)NTOK*2*DIN];   // interleaved: cols 0..1023=Q, 1024..2047=K
__device__ bf16 g_QKlo[(size_t)NTOK*2*DIN];
__device__ bf16 g_VThi[(size_t)DIN*NTOK];     // V^T: [e][b*S+s]
__device__ bf16 g_VTlo[(size_t)DIN*NTOK];
__device__ float g_S[(size_t)BATCH*SLEN*SLEN];    // raw scores (unscaled)
__device__ bf16 g_Phi[(size_t)BATCH*SLEN*SLEN];
__device__ bf16 g_Plo[(size_t)BATCH*SLEN*SLEN];

// ---------------- helpers ----------------
__device__ __forceinline__ uint32_t smem_u32(const void* p) {
    return (uint32_t)__cvta_generic_to_shared(p);
}
#define CP_COMMIT() asm volatile("cp.async.commit_group;\n" ::: "memory")
#define CP_WAIT1()  asm volatile("cp.async.wait_group 1;\n" ::: "memory")
#define CP_WAIT0()  asm volatile("cp.async.wait_group 0;\n" ::: "memory")

__device__ __forceinline__ void ldsm4(uint32_t* r, uint32_t addr) {
    asm volatile("ldmatrix.sync.aligned.m8n8.x4.shared.b16 {%0,%1,%2,%3}, [%4];"
        : "=r"(r[0]), "=r"(r[1]), "=r"(r[2]), "=r"(r[3]) : "r"(addr));
}
__device__ __forceinline__ void mma_bf16(float* d, const uint32_t* a, const uint32_t* b) {
    asm volatile(
        "mma.sync.aligned.m16n8k16.row.col.f32.bf16.bf16.f32 "
        "{%0,%1,%2,%3}, {%4,%5,%6,%7}, {%8,%9}, {%0,%1,%2,%3};"
        : "+f"(d[0]), "+f"(d[1]), "+f"(d[2]), "+f"(d[3])
        : "r"(a[0]), "r"(a[1]), "r"(a[2]), "r"(a[3]), "r"(b[0]), "r"(b[1]));
}

// cp.async a [128 x 64 bf16] tile (128B rows) into swizzled smem; 128 threads
__device__ __forceinline__ void load_tile(const bf16* __restrict__ g, int ld,
                                          int row0, int k0, uint32_t sdst, int tid)
{
#pragma unroll
    for (int c = tid; c < 128 * 8; c += 128) {
        int r = c >> 3, col = c & 7;
        const void* src = (const void*)(g + (size_t)(row0 + r) * ld + k0 + col * 8);
        uint32_t dst = sdst + ((uint32_t)r << 7) + ((uint32_t)(col ^ (r & 7)) << 4);
        asm volatile("cp.async.cg.shared.global [%0], [%1], 16;\n" :: "r"(dst), "l"(src));
    }
}

// ---------------------------------------------------------------------------
// Split-bf16 3-pass warp-MMA GEMM: D[m][n] = sum_k A[m][k]*B[n][k]
// D = Ahi*Bhi + Ahi*Blo + Alo*Bhi (all K-major operands)
// mode 0: fp32 output; mode 1: split hi/lo bf16 output
// causal 0: none; 1: triangular-compacted scores grid (bx,by from linear id);
//        2: kEnd=(by+1)*BM (PV);
//        3: like 2 but with launch-order load-balancing remap of by
// 128 threads, warps 2m x 2n, warp tile 64x64.
// ---------------------------------------------------------------------------
__global__ void __launch_bounds__(128)
gemm3(const bf16* __restrict__ Ahi, const bf16* __restrict__ Alo,
      const bf16* __restrict__ Bhi, const bf16* __restrict__ Blo,
      int K, int lda, int ldb,
      long long sAz, long long sBz, long long sCz,
      float* __restrict__ Cf, bf16* __restrict__ Chi, bf16* __restrict__ Clo,
      int ldc, int mode, int causal)
{
    const int z = blockIdx.z;
    int bx = blockIdx.x;
    int by = blockIdx.y;
    if (causal == 1) {
        // linear lower-triangle index -> (by, bx), by >= bx
        int t = blockIdx.x;
        by = (int)((sqrtf(8.0f * t + 1.0f) - 1.0f) * 0.5f);
        while ((by + 1) * (by + 2) / 2 <= t) by++;
        while (by * (by + 1) / 2 > t) by--;
        bx = t - by * (by + 1) / 2;
    } else if (causal == 3) {   // interleave heavy (high-by) with light (low-by)
        const int n = gridDim.y;
        by = (by & 1) ? (n - 1 - (by >> 1)) : (by >> 1);
    }
    const int m0 = by * BM, n0 = bx * BN;

    const int kEnd = (causal >= 2) ? (by + 1) * BM : K;
    const int nit = kEnd / BK;

    Ahi += (size_t)z * sAz;  Alo += (size_t)z * sAz;
    Bhi += (size_t)z * sBz;  Blo += (size_t)z * sBz;

    extern __shared__ char smem_raw[];
    const uint32_t sbase = (smem_u32(smem_raw) + 1023u) & ~1023u;

    const int tid = threadIdx.x;
    const int wid = tid >> 5, lid = tid & 31;
    const int warp_m = wid >> 1;        // 0..1 (64 rows each)
    const int warp_n = wid & 1;         // 0..1 (64 cols each)

    float acc[4][8][4];
#pragma unroll
    for (int i = 0; i < 4; i++)
#pragma unroll
        for (int j = 0; j < 8; j++)
#pragma unroll
            for (int q = 0; q < 4; q++) acc[i][j][q] = 0.0f;

    // ldmatrix address components
    const int a_row_base = warp_m * 64 + (lid & 15);
    const int a_chalf = lid >> 4;
    const int b_row_base = warp_n * 64 + (lid >> 4) * 8 + (lid & 7);
    const int b_chalf = (lid >> 3) & 1;

    // prologue: stage 0
    load_tile(Ahi, lda, m0, 0, sbase + SM_A_HI, tid);
    load_tile(Alo, lda, m0, 0, sbase + SM_A_LO, tid);
    load_tile(Bhi, ldb, n0, 0, sbase + SM_B_HI, tid);
    load_tile(Blo, ldb, n0, 0, sbase + SM_B_LO, tid);
    CP_COMMIT();

    for (int it = 0; it < nit; it++) {
        const int p = it & 1;
        if (it + 1 < nit) {
            const uint32_t sb = sbase + (p ^ 1) * STAGE_BYTES;
            const int k0 = (it + 1) * BK;
            load_tile(Ahi, lda, m0, k0, sb + SM_A_HI, tid);
            load_tile(Alo, lda, m0, k0, sb + SM_A_LO, tid);
            load_tile(Bhi, ldb, n0, k0, sb + SM_B_HI, tid);
            load_tile(Blo, ldb, n0, k0, sb + SM_B_LO, tid);
            CP_COMMIT();
            CP_WAIT1();
        } else {
            CP_WAIT0();
        }
        __syncthreads();

        const uint32_t sb = sbase + p * STAGE_BYTES;
#pragma unroll
        for (int kk = 0; kk < 4; kk++) {
            uint32_t ah[4][4], al[4][4];
#pragma unroll
            for (int im = 0; im < 4; im++) {
                const int row = a_row_base + im * 16;
                const int c16 = kk * 2 + a_chalf;
                const uint32_t off = ((uint32_t)row << 7) + ((uint32_t)(c16 ^ (row & 7)) << 4);
                ldsm4(ah[im], sb + SM_A_HI + off);
                ldsm4(al[im], sb + SM_A_LO + off);
            }
#pragma unroll
            for (int jn = 0; jn < 4; jn++) {
                uint32_t bh[4], bl[4];
                const int n = b_row_base + jn * 16;
                const int c16 = kk * 2 + b_chalf;
                const uint32_t off = ((uint32_t)n << 7) + ((uint32_t)(c16 ^ (n & 7)) << 4);
                ldsm4(bh, sb + SM_B_HI + off);
                ldsm4(bl, sb + SM_B_LO + off);
#pragma unroll
                for (int im = 0; im < 4; im++) {
#pragma unroll
                    for (int h = 0; h < 2; h++) {
                        float* d = acc[im][jn * 2 + h];
                        mma_bf16(d, ah[im], bh + 2 * h);
                        mma_bf16(d, ah[im], bl + 2 * h);
                        mma_bf16(d, al[im], bh + 2 * h);
                    }
                }
            }
        }
        __syncthreads();
    }

    // epilogue
    const int tq = lid >> 2;   // 0..7
    const int tr = lid & 3;    // 0..3
    const size_t cbase = (size_t)z * (size_t)sCz;
#pragma unroll
    for (int im = 0; im < 4; im++) {
#pragma unroll
        for (int j = 0; j < 8; j++) {
            const int r0 = m0 + warp_m * 64 + im * 16 + tq;
            const int c0 = n0 + warp_n * 64 + j * 8 + tr * 2;
            const float* d = acc[im][j];
            if (mode == 0) {
                *(float2*)(Cf + cbase + (size_t)r0 * ldc + c0)       = make_float2(d[0], d[1]);
                *(float2*)(Cf + cbase + (size_t)(r0 + 8) * ldc + c0) = make_float2(d[2], d[3]);
            } else {
#pragma unroll
                for (int rr = 0; rr < 2; rr++) {
                    float va = d[2 * rr], vb = d[2 * rr + 1];
                    bf16 ha = __float2bfloat16(va);
                    bf16 hb = __float2bfloat16(vb);
                    __nv_bfloat162 hv; hv.x = ha; hv.y = hb;
                    __nv_bfloat162 lv;
                    lv.x = __float2bfloat16(va - __bfloat162float(ha));
                    lv.y = __float2bfloat16(vb - __bfloat162float(hb));
                    const size_t o = cbase + (size_t)(r0 + 8 * rr) * ldc + c0;
                    *(uint32_t*)(Chi + o) = *(uint32_t*)&hv;
                    *(uint32_t*)(Clo + o) = *(uint32_t*)&lv;
                }
            }
        }
    }
}

// ---------------------------------------------------------------------------
__global__ void __launch_bounds__(256)
split_f32(const float* __restrict__ x, bf16* __restrict__ hi, bf16* __restrict__ lo, int n4)
{
    int i = blockIdx.x * 256 + threadIdx.x;
    if (i >= n4) return;
    float4 v = ((const float4*)x)[i];
    float f[4] = {v.x, v.y, v.z, v.w};
    bf16 h[4]; bf16 l[4];
#pragma unroll
    for (int j = 0; j < 4; j++) {
        h[j] = __float2bfloat16(f[j]);
        l[j] = __float2bfloat16(f[j] - __bfloat162float(h[j]));
    }
    ((uint2*)hi)[i] = *(uint2*)h;
    ((uint2*)lo)[i] = *(uint2*)l;
}

// ---------------------------------------------------------------------------
// All three weights: W [DIN x DIN] fp32 -> W^T hi/lo bf16 (z selects matrix)
// ---------------------------------------------------------------------------
__global__ void __launch_bounds__(256)
transpose_split3(const float* __restrict__ W0, const float* __restrict__ W1,
                 const float* __restrict__ W2, bf16* __restrict__ Thi,
                 bf16* __restrict__ Tlo)
{
    const int zz = blockIdx.z;
    const float* W = (zz == 0) ? W0 : (zz == 1) ? W1 : W2;
    const size_t zoff = (size_t)zz * DIN * DIN;

    __shared__ float t[32][33];
    const int bx = blockIdx.x * 32, by = blockIdx.y * 32;
    const int x = threadIdx.x, y = threadIdx.y;   // 32 x 8
#pragma unroll
    for (int i = 0; i < 32; i += 8)
        t[y + i][x] = W[(size_t)(by + y + i) * DIN + bx + x];
    __syncthreads();
#pragma unroll
    for (int i = 0; i < 32; i += 8) {
        float v = t[x][y + i];
        bf16 h = __float2bfloat16(v);
        bf16 l = __float2bfloat16(v - __bfloat162float(h));
        Thi[zoff + (size_t)(bx + y + i) * DIN + by + x] = h;
        Tlo[zoff + (size_t)(bx + y + i) * DIN + by + x] = l;
    }
}

// ---------------------------------------------------------------------------
// Softmax over k<=q of scale*S, emit split-bf16 P, zero-pad to 128 boundary
// ---------------------------------------------------------------------------
__global__ void __launch_bounds__(256)
softmax_split(const float* __restrict__ S, bf16* __restrict__ Phi, bf16* __restrict__ Plo,
              float scale)
{
    const int row = blockIdx.x;                // 0 .. B*SLEN-1
    const int q = row & (SLEN - 1);
    const float* p = S + (size_t)row * SLEN;
    const int L = q + 1;
    const int t = threadIdx.x;

    float v[8];
    float mx = -INFINITY;
#pragma unroll
    for (int i = 0; i < 8; i++) {
        int idx = t + i * 256;
        v[i] = (idx < L) ? p[idx] * scale : -INFINITY;
        mx = fmaxf(mx, v[i]);
    }

    __shared__ float redm[8];
    __shared__ float reds[8];

#pragma unroll
    for (int o = 16; o; o >>= 1) mx = fmaxf(mx, __shfl_xor_sync(0xFFFFFFFFu, mx, o));
    if ((t & 31) == 0) redm[t >> 5] = mx;
    __syncthreads();
    float m = redm[0];
#pragma unroll
    for (int i = 1; i < 8; i++) m = fmaxf(m, redm[i]);

    float s = 0.0f;
#pragma unroll
    for (int i = 0; i < 8; i++) {
        float e = __expf(v[i] - m);
        v[i] = e;
        s += e;
    }
#pragma unroll
    for (int o = 16; o; o >>= 1) s += __shfl_xor_sync(0xFFFFFFFFu, s, o);
    if ((t & 31) == 0) reds[t >> 5] = s;
    __syncthreads();
    float tot = 0.0f;
#pragma unroll
    for (int i = 0; i < 8; i++) tot += reds[i];
    const float inv = 1.0f / tot;

    bf16* ph = Phi + (size_t)row * SLEN;
    bf16* pl = Plo + (size_t)row * SLEN;
    const int pad = (L + 127) & ~127;
#pragma unroll
    for (int i = 0; i < 8; i++) {
        int idx = t + i * 256;
        if (idx < L) {
            float w = v[i] * inv;
            bf16 h = __float2bfloat16(w);
            ph[idx] = h;
            pl[idx] = __float2bfloat16(w - __bfloat162float(h));
        } else if (idx < pad) {
            ph[idx] = __float2bfloat16(0.0f);
            pl[idx] = __float2bfloat16(0.0f);
        }
    }
}

// ---------------------------------------------------------------------------
extern "C" void kernel_launch(void* const* d_in, const int* in_sizes, int n_in,
                              void* d_out, int out_size)
{
    const float* x  = (const float*)d_in[0];
    const float* Wq = (const float*)d_in[1];
    const float* Wk = (const float*)d_in[2];
    const float* Wv = (const float*)d_in[3];
    float* out = (float*)d_out;
    (void)in_sizes; (void)n_in; (void)out_size;

    cudaFuncSetAttribute(gemm3, cudaFuncAttributeMaxDynamicSharedMemorySize, SMEM_REQ);

    bf16 *Xhi, *Xlo, *WThi, *WTlo, *QKhi, *QKlo, *VThi, *VTlo, *Phi, *Plo;
    float *Sp;
    cudaGetSymbolAddress((void**)&Xhi, g_Xhi);
    cudaGetSymbolAddress((void**)&Xlo, g_Xlo);
    cudaGetSymbolAddress((void**)&WThi, g_WThi);
    cudaGetSymbolAddress((void**)&WTlo, g_WTlo);
    cudaGetSymbolAddress((void**)&QKhi, g_QKhi);
    cudaGetSymbolAddress((void**)&QKlo, g_QKlo);
    cudaGetSymbolAddress((void**)&VThi, g_VThi);
    cudaGetSymbolAddress((void**)&VTlo, g_VTlo);
    cudaGetSymbolAddress((void**)&Sp, g_S);
    cudaGetSymbolAddress((void**)&Phi, g_Phi);
    cudaGetSymbolAddress((void**)&Plo, g_Plo);

    const size_t WSTRIDE = (size_t)DIN * DIN;

    // 1) split x
    split_f32<<<(NTOK * DIN / 4) / 256, 256>>>(x, Xhi, Xlo, NTOK * DIN / 4);

    // 2) transpose + split the three weights in one launch
    {
        dim3 g(DIN / 32, DIN / 32, 3), b(32, 8);
        transpose_split3<<<g, b>>>(Wq, Wk, Wv, WThi, WTlo);
    }

    // 3) merged QK projection: [8192 x 1024] @ [1024 x 2048] -> QK interleaved
    {
        dim3 g(2 * DIN / BN, NTOK / BM, 1);   // 16 x 64
        gemm3<<<g, 128, SMEM_REQ>>>(Xhi, Xlo, WThi, WTlo,
                                    DIN, DIN, DIN, 0, 0, 0,
                                    nullptr, QKhi, QKlo, 2 * DIN, 1, 0);
    }

    // 4) V^T = (x @ Wv)^T : A = Wv^T [1024x1024], B = X [8192x1024]
    {
        dim3 g(NTOK / BN, DIN / BM, 1);   // 64 x 8
        gemm3<<<g, 128, SMEM_REQ>>>(WThi + 2 * WSTRIDE, WTlo + 2 * WSTRIDE, Xhi, Xlo,
                                    DIN, DIN, DIN, 0, 0, 0,
                                    nullptr, VThi, VTlo, NTOK, 1, 0);
    }

    // 5) scores S[q][k] = Q . K per batch (unscaled), triangular-compacted grid
    //    Q = QK cols [0,1024), K = QK cols [1024,2048), both ld = 2048
    {
        const int ntiles = (SLEN / BM) * (SLEN / BM + 1) / 2;   // 136
        dim3 g(ntiles, 1, BATCH);
        gemm3<<<g, 128, SMEM_REQ>>>(QKhi, QKlo, QKhi + DIN, QKlo + DIN,
                                    DIN, 2 * DIN, 2 * DIN,
                                    (long long)SLEN * 2 * DIN, (long long)SLEN * 2 * DIN,
                                    (long long)SLEN * SLEN,
                                    Sp, nullptr, nullptr, SLEN, 0, 1);
    }

    // 6) softmax + split P
    softmax_split<<<BATCH * SLEN, 256>>>(Sp, Phi, Plo, 0.03125f);

    // 7) out = P @ V, causal k-bound + load-balanced by remap
    {
        dim3 g(DIN / BN, SLEN / BM, BATCH);    // 8 x 16 x 4
        gemm3<<<g, 128, SMEM_REQ>>>(Phi, Plo, VThi, VTlo,
                                    SLEN, SLEN, NTOK,
                                    (long long)SLEN * SLEN, (long long)SLEN,
                                    (long long)SLEN * DIN,
                                    out, nullptr, nullptr, DIN, 0, 3);
    }
}

// round 8
// speedup vs baseline: 1.0917x; 1.0917x over previous
#include <cuda_runtime.h>
#include <cuda_bf16.h>
#include <cstdint>
#include <cstddef>

typedef __nv_bfloat16 bf16;

#define BATCH 4
#define SLEN  2048
#define DIN   1024
#define NTOK  (BATCH*SLEN)

// GEMM tile config: BM=64, BN=128, BK=64 -> stage 48KB, 2 stages, 2 CTAs/SM
#define BM 64
#define BN 128
#define BK 64
#define A_BYTES (64*128)
#define B_BYTES (128*128)
#define STAGE_BYTES (2*A_BYTES + 2*B_BYTES)   // 48KB
#define SM_A_HI 0
#define SM_A_LO (A_BYTES)
#define SM_B_HI (2*A_BYTES)
#define SM_B_LO (2*A_BYTES + B_BYTES)
#define SMEM_REQ (1024 + 2*STAGE_BYTES)

// ---------------- scratch (device globals; no allocs allowed) ----------------
__device__ bf16 g_Xhi[(size_t)NTOK*DIN];
__device__ bf16 g_Xlo[(size_t)NTOK*DIN];
__device__ bf16 g_WThi[3][(size_t)DIN*DIN];   // W^T split; [0],[1] contiguous = QK merged B
__device__ bf16 g_WTlo[3][(size_t)DIN*DIN];
__device__ bf16 g_QKhi[(size_t)NTOK*2*DIN];   // interleaved: cols 0..1023=Q, 1024..2047=K
__device__ bf16 g_QKlo[(size_t)NTOK*2*DIN];
__device__ bf16 g_VThi[(size_t)DIN*NTOK];     // V^T: [e][b*S+s]
__device__ bf16 g_VTlo[(size_t)DIN*NTOK];
__device__ float g_S[(size_t)BATCH*SLEN*SLEN];    // raw scores (unscaled)
__device__ bf16 g_Phi[(size_t)BATCH*SLEN*SLEN];
__device__ bf16 g_Plo[(size_t)BATCH*SLEN*SLEN];

// ---------------- helpers ----------------
__device__ __forceinline__ uint32_t smem_u32(const void* p) {
    return (uint32_t)__cvta_generic_to_shared(p);
}
#define CP_COMMIT() asm volatile("cp.async.commit_group;\n" ::: "memory")
#define CP_WAIT1()  asm volatile("cp.async.wait_group 1;\n" ::: "memory")
#define CP_WAIT0()  asm volatile("cp.async.wait_group 0;\n" ::: "memory")

__device__ __forceinline__ void ldsm4(uint32_t* r, uint32_t addr) {
    asm volatile("ldmatrix.sync.aligned.m8n8.x4.shared.b16 {%0,%1,%2,%3}, [%4];"
        : "=r"(r[0]), "=r"(r[1]), "=r"(r[2]), "=r"(r[3]) : "r"(addr));
}
__device__ __forceinline__ void mma_bf16(float* d, const uint32_t* a, const uint32_t* b) {
    asm volatile(
        "mma.sync.aligned.m16n8k16.row.col.f32.bf16.bf16.f32 "
        "{%0,%1,%2,%3}, {%4,%5,%6,%7}, {%8,%9}, {%0,%1,%2,%3};"
        : "+f"(d[0]), "+f"(d[1]), "+f"(d[2]), "+f"(d[3])
        : "r"(a[0]), "r"(a[1]), "r"(a[2]), "r"(a[3]), "r"(b[0]), "r"(b[1]));
}

// cp.async a [ROWS x 64 bf16] tile (128B rows) into swizzled smem; 128 threads
template<int ROWS>
__device__ __forceinline__ void load_tile(const bf16* __restrict__ g, int ld,
                                          int row0, int k0, uint32_t sdst, int tid)
{
#pragma unroll
    for (int c = tid; c < ROWS * 8; c += 128) {
        int r = c >> 3, col = c & 7;
        const void* src = (const void*)(g + (size_t)(row0 + r) * ld + k0 + col * 8);
        uint32_t dst = sdst + ((uint32_t)r << 7) + ((uint32_t)(col ^ (r & 7)) << 4);
        asm volatile("cp.async.cg.shared.global [%0], [%1], 16;\n" :: "r"(dst), "l"(src));
    }
}

// ---------------------------------------------------------------------------
// Split-bf16 3-pass warp-MMA GEMM: D[m][n] = sum_k A[m][k]*B[n][k]
// D = Ahi*Bhi + Ahi*Blo + Alo*Bhi (all K-major operands)
// mode 0: fp32 output; mode 1: split hi/lo bf16 output
// causal 0: none; 1: skip tiles above diagonal (scores);
//        2: kEnd=(by+1)*BM (PV); 3: like 2 + load-balancing remap of by
// 128 threads, warps 2m x 2n, warp tile 32x64.
// Register-level fragment double-buffering inside the kk loop hides LDS latency.
// ---------------------------------------------------------------------------
__global__ void __launch_bounds__(128)
gemm3(const bf16* __restrict__ Ahi, const bf16* __restrict__ Alo,
      const bf16* __restrict__ Bhi, const bf16* __restrict__ Blo,
      int K, int lda, int ldb,
      long long sAz, long long sBz, long long sCz,
      float* __restrict__ Cf, bf16* __restrict__ Chi, bf16* __restrict__ Clo,
      int ldc, int mode, int causal)
{
    const int bx = blockIdx.x, z = blockIdx.z;
    int by = blockIdx.y;
    if (causal == 3) {   // interleave heavy (high-by) with light (low-by) CTAs
        const int n = gridDim.y;
        by = (by & 1) ? (n - 1 - (by >> 1)) : (by >> 1);
    }
    const int m0 = by * BM, n0 = bx * BN;
    if (causal == 1 && n0 > m0 + (BM - 1)) return;

    const int kEnd = (causal >= 2) ? (by + 1) * BM : K;
    const int nit = kEnd / BK;

    Ahi += (size_t)z * sAz;  Alo += (size_t)z * sAz;
    Bhi += (size_t)z * sBz;  Blo += (size_t)z * sBz;

    extern __shared__ char smem_raw[];
    const uint32_t sbase = (smem_u32(smem_raw) + 1023u) & ~1023u;

    const int tid = threadIdx.x;
    const int wid = tid >> 5, lid = tid & 31;
    const int warp_m = wid >> 1;        // 0..1 (32 rows each)
    const int warp_n = wid & 1;         // 0..1 (64 cols each)

    float acc[2][8][4];
#pragma unroll
    for (int i = 0; i < 2; i++)
#pragma unroll
        for (int j = 0; j < 8; j++)
#pragma unroll
            for (int q = 0; q < 4; q++) acc[i][j][q] = 0.0f;

    // ldmatrix address components
    const int a_row_base = warp_m * 32 + (lid & 15);
    const int a_chalf = lid >> 4;
    const int b_row_base = warp_n * 64 + (lid >> 4) * 8 + (lid & 7);
    const int b_chalf = (lid >> 3) & 1;

    // prologue: stage 0
    load_tile<BM>(Ahi, lda, m0, 0, sbase + SM_A_HI, tid);
    load_tile<BM>(Alo, lda, m0, 0, sbase + SM_A_LO, tid);
    load_tile<BN>(Bhi, ldb, n0, 0, sbase + SM_B_HI, tid);
    load_tile<BN>(Blo, ldb, n0, 0, sbase + SM_B_LO, tid);
    CP_COMMIT();

    // fragment register double buffers
    uint32_t ah[2][2][4], al[2][2][4];   // [buf][im][4]
    uint32_t bh[2][4][4], bl[2][4][4];   // [buf][jn][4]

    for (int it = 0; it < nit; it++) {
        const int p = it & 1;
        if (it + 1 < nit) {
            const uint32_t sb = sbase + (p ^ 1) * STAGE_BYTES;
            const int k0 = (it + 1) * BK;
            load_tile<BM>(Ahi, lda, m0, k0, sb + SM_A_HI, tid);
            load_tile<BM>(Alo, lda, m0, k0, sb + SM_A_LO, tid);
            load_tile<BN>(Bhi, ldb, n0, k0, sb + SM_B_HI, tid);
            load_tile<BN>(Blo, ldb, n0, k0, sb + SM_B_LO, tid);
            CP_COMMIT();
            CP_WAIT1();
        } else {
            CP_WAIT0();
        }
        __syncthreads();

        const uint32_t sb = sbase + p * STAGE_BYTES;

        // preload kk=0 fragments into buffer 0
#pragma unroll
        for (int im = 0; im < 2; im++) {
            const int row = a_row_base + im * 16;
            const uint32_t off = ((uint32_t)row << 7) + ((uint32_t)(a_chalf ^ (row & 7)) << 4);
            ldsm4(ah[0][im], sb + SM_A_HI + off);
            ldsm4(al[0][im], sb + SM_A_LO + off);
        }
#pragma unroll
        for (int jn = 0; jn < 4; jn++) {
            const int n = b_row_base + jn * 16;
            const uint32_t off = ((uint32_t)n << 7) + ((uint32_t)(b_chalf ^ (n & 7)) << 4);
            ldsm4(bh[0][jn], sb + SM_B_HI + off);
            ldsm4(bl[0][jn], sb + SM_B_LO + off);
        }

#pragma unroll
        for (int kk = 0; kk < 4; kk++) {
            const int cur = kk & 1, nxt = cur ^ 1;
            if (kk < 3) {   // prefetch kk+1 fragments while MMAs of kk run
#pragma unroll
                for (int im = 0; im < 2; im++) {
                    const int row = a_row_base + im * 16;
                    const int c16 = (kk + 1) * 2 + a_chalf;
                    const uint32_t off = ((uint32_t)row << 7) + ((uint32_t)(c16 ^ (row & 7)) << 4);
                    ldsm4(ah[nxt][im], sb + SM_A_HI + off);
                    ldsm4(al[nxt][im], sb + SM_A_LO + off);
                }
#pragma unroll
                for (int jn = 0; jn < 4; jn++) {
                    const int n = b_row_base + jn * 16;
                    const int c16 = (kk + 1) * 2 + b_chalf;
                    const uint32_t off = ((uint32_t)n << 7) + ((uint32_t)(c16 ^ (n & 7)) << 4);
                    ldsm4(bh[nxt][jn], sb + SM_B_HI + off);
                    ldsm4(bl[nxt][jn], sb + SM_B_LO + off);
                }
            }
#pragma unroll
            for (int jn = 0; jn < 4; jn++) {
#pragma unroll
                for (int im = 0; im < 2; im++) {
#pragma unroll
                    for (int h = 0; h < 2; h++) {
                        float* d = acc[im][jn * 2 + h];
                        mma_bf16(d, ah[cur][im], bh[cur][jn] + 2 * h);
                        mma_bf16(d, ah[cur][im], bl[cur][jn] + 2 * h);
                        mma_bf16(d, al[cur][im], bh[cur][jn] + 2 * h);
                    }
                }
            }
        }
        __syncthreads();
    }

    // epilogue
    const int tq = lid >> 2;   // 0..7
    const int tr = lid & 3;    // 0..3
    const size_t cbase = (size_t)z * (size_t)sCz;
#pragma unroll
    for (int im = 0; im < 2; im++) {
#pragma unroll
        for (int j = 0; j < 8; j++) {
            const int r0 = m0 + warp_m * 32 + im * 16 + tq;
            const int c0 = n0 + warp_n * 64 + j * 8 + tr * 2;
            const float* d = acc[im][j];
            if (mode == 0) {
                *(float2*)(Cf + cbase + (size_t)r0 * ldc + c0)       = make_float2(d[0], d[1]);
                *(float2*)(Cf + cbase + (size_t)(r0 + 8) * ldc + c0) = make_float2(d[2], d[3]);
            } else {
#pragma unroll
                for (int rr = 0; rr < 2; rr++) {
                    float va = d[2 * rr], vb = d[2 * rr + 1];
                    bf16 ha = __float2bfloat16(va);
                    bf16 hb = __float2bfloat16(vb);
                    __nv_bfloat162 hv; hv.x = ha; hv.y = hb;
                    __nv_bfloat162 lv;
                    lv.x = __float2bfloat16(va - __bfloat162float(ha));
                    lv.y = __float2bfloat16(vb - __bfloat162float(hb));
                    const size_t o = cbase + (size_t)(r0 + 8 * rr) * ldc + c0;
                    *(uint32_t*)(Chi + o) = *(uint32_t*)&hv;
                    *(uint32_t*)(Clo + o) = *(uint32_t*)&lv;
                }
            }
        }
    }
}

// ---------------------------------------------------------------------------
__global__ void __launch_bounds__(256)
split_f32(const float* __restrict__ x, bf16* __restrict__ hi, bf16* __restrict__ lo, int n4)
{
    int i = blockIdx.x * 256 + threadIdx.x;
    if (i >= n4) return;
    float4 v = ((const float4*)x)[i];
    float f[4] = {v.x, v.y, v.z, v.w};
    bf16 h[4]; bf16 l[4];
#pragma unroll
    for (int j = 0; j < 4; j++) {
        h[j] = __float2bfloat16(f[j]);
        l[j] = __float2bfloat16(f[j] - __bfloat162float(h[j]));
    }
    ((uint2*)hi)[i] = *(uint2*)h;
    ((uint2*)lo)[i] = *(uint2*)l;
}

// ---------------------------------------------------------------------------
// All three weights: W [DIN x DIN] fp32 -> W^T hi/lo bf16 (z selects matrix)
// ---------------------------------------------------------------------------
__global__ void __launch_bounds__(256)
transpose_split3(const float* __restrict__ W0, const float* __restrict__ W1,
                 const float* __restrict__ W2, bf16* __restrict__ Thi,
                 bf16* __restrict__ Tlo)
{
    const int zz = blockIdx.z;
    const float* W = (zz == 0) ? W0 : (zz == 1) ? W1 : W2;
    const size_t zoff = (size_t)zz * DIN * DIN;

    __shared__ float t[32][33];
    const int bx = blockIdx.x * 32, by = blockIdx.y * 32;
    const int x = threadIdx.x, y = threadIdx.y;   // 32 x 8
#pragma unroll
    for (int i = 0; i < 32; i += 8)
        t[y + i][x] = W[(size_t)(by + y + i) * DIN + bx + x];
    __syncthreads();
#pragma unroll
    for (int i = 0; i < 32; i += 8) {
        float v = t[x][y + i];
        bf16 h = __float2bfloat16(v);
        bf16 l = __float2bfloat16(v - __bfloat162float(h));
        Thi[zoff + (size_t)(bx + y + i) * DIN + by + x] = h;
        Tlo[zoff + (size_t)(bx + y + i) * DIN + by + x] = l;
    }
}

// ---------------------------------------------------------------------------
// Softmax over k<=q of scale*S, emit split-bf16 P, zero-pad to 64 boundary
// ---------------------------------------------------------------------------
__global__ void __launch_bounds__(256)
softmax_split(const float* __restrict__ S, bf16* __restrict__ Phi, bf16* __restrict__ Plo,
              float scale)
{
    const int row = blockIdx.x;                // 0 .. B*SLEN-1
    const int q = row & (SLEN - 1);
    const float* p = S + (size_t)row * SLEN;
    const int L = q + 1;
    const int t = threadIdx.x;

    float v[8];
    float mx = -INFINITY;
#pragma unroll
    for (int i = 0; i < 8; i++) {
        int idx = t + i * 256;
        v[i] = (idx < L) ? p[idx] * scale : -INFINITY;
        mx = fmaxf(mx, v[i]);
    }

    __shared__ float redm[8];
    __shared__ float reds[8];

#pragma unroll
    for (int o = 16; o; o >>= 1) mx = fmaxf(mx, __shfl_xor_sync(0xFFFFFFFFu, mx, o));
    if ((t & 31) == 0) redm[t >> 5] = mx;
    __syncthreads();
    float m = redm[0];
#pragma unroll
    for (int i = 1; i < 8; i++) m = fmaxf(m, redm[i]);

    float s = 0.0f;
#pragma unroll
    for (int i = 0; i < 8; i++) {
        float e = __expf(v[i] - m);
        v[i] = e;
        s += e;
    }
#pragma unroll
    for (int o = 16; o; o >>= 1) s += __shfl_xor_sync(0xFFFFFFFFu, s, o);
    if ((t & 31) == 0) reds[t >> 5] = s;
    __syncthreads();
    float tot = 0.0f;
#pragma unroll
    for (int i = 0; i < 8; i++) tot += reds[i];
    const float inv = 1.0f / tot;

    bf16* ph = Phi + (size_t)row * SLEN;
    bf16* pl = Plo + (size_t)row * SLEN;
    const int pad = (L + 63) & ~63;
#pragma unroll
    for (int i = 0; i < 8; i++) {
        int idx = t + i * 256;
        if (idx < L) {
            float w = v[i] * inv;
            bf16 h = __float2bfloat16(w);
            ph[idx] = h;
            pl[idx] = __float2bfloat16(w - __bfloat162float(h));
        } else if (idx < pad) {
            ph[idx] = __float2bfloat16(0.0f);
            pl[idx] = __float2bfloat16(0.0f);
        }
    }
}

// ---------------------------------------------------------------------------
extern "C" void kernel_launch(void* const* d_in, const int* in_sizes, int n_in,
                              void* d_out, int out_size)
{
    const float* x  = (const float*)d_in[0];
    const float* Wq = (const float*)d_in[1];
    const float* Wk = (const float*)d_in[2];
    const float* Wv = (const float*)d_in[3];
    float* out = (float*)d_out;
    (void)in_sizes; (void)n_in; (void)out_size;

    cudaFuncSetAttribute(gemm3, cudaFuncAttributeMaxDynamicSharedMemorySize, SMEM_REQ);

    bf16 *Xhi, *Xlo, *WThi, *WTlo, *QKhi, *QKlo, *VThi, *VTlo, *Phi, *Plo;
    float *Sp;
    cudaGetSymbolAddress((void**)&Xhi, g_Xhi);
    cudaGetSymbolAddress((void**)&Xlo, g_Xlo);
    cudaGetSymbolAddress((void**)&WThi, g_WThi);
    cudaGetSymbolAddress((void**)&WTlo, g_WTlo);
    cudaGetSymbolAddress((void**)&QKhi, g_QKhi);
    cudaGetSymbolAddress((void**)&QKlo, g_QKlo);
    cudaGetSymbolAddress((void**)&VThi, g_VThi);
    cudaGetSymbolAddress((void**)&VTlo, g_VTlo);
    cudaGetSymbolAddress((void**)&Sp, g_S);
    cudaGetSymbolAddress((void**)&Phi, g_Phi);
    cudaGetSymbolAddress((void**)&Plo, g_Plo);

    const size_t WSTRIDE = (size_t)DIN * DIN;

    // 1) split x
    split_f32<<<(NTOK * DIN / 4) / 256, 256>>>(x, Xhi, Xlo, NTOK * DIN / 4);

    // 2) transpose + split the three weights in one launch
    {
        dim3 g(DIN / 32, DIN / 32, 3), b(32, 8);
        transpose_split3<<<g, b>>>(Wq, Wk, Wv, WThi, WTlo);
    }

    // 3) merged QK projection: [8192 x 1024] @ [1024 x 2048] -> QK interleaved
    {
        dim3 g(2 * DIN / BN, NTOK / BM, 1);   // 16 x 128
        gemm3<<<g, 128, SMEM_REQ>>>(Xhi, Xlo, WThi, WTlo,
                                    DIN, DIN, DIN, 0, 0, 0,
                                    nullptr, QKhi, QKlo, 2 * DIN, 1, 0);
    }

    // 4) V^T = (x @ Wv)^T : A = Wv^T [1024x1024], B = X [8192x1024]
    {
        dim3 g(NTOK / BN, DIN / BM, 1);   // 64 x 16
        gemm3<<<g, 128, SMEM_REQ>>>(WThi + 2 * WSTRIDE, WTlo + 2 * WSTRIDE, Xhi, Xlo,
                                    DIN, DIN, DIN, 0, 0, 0,
                                    nullptr, VThi, VTlo, NTOK, 1, 0);
    }

    // 5) scores S[q][k] = Q . K per batch (unscaled), causal tile skip
    //    Q = QK cols [0,1024), K = QK cols [1024,2048), both ld = 2048
    {
        dim3 g(SLEN / BN, SLEN / BM, BATCH);   // 16 x 32 x 4
        gemm3<<<g, 128, SMEM_REQ>>>(QKhi, QKlo, QKhi + DIN, QKlo + DIN,
                                    DIN, 2 * DIN, 2 * DIN,
                                    (long long)SLEN * 2 * DIN, (long long)SLEN * 2 * DIN,
                                    (long long)SLEN * SLEN,
                                    Sp, nullptr, nullptr, SLEN, 0, 1);
    }

    // 6) softmax + split P
    softmax_split<<<BATCH * SLEN, 256>>>(Sp, Phi, Plo, 0.03125f);

    // 7) out = P @ V, causal k-bound + load-balanced by remap
    {
        dim3 g(DIN / BN, SLEN / BM, BATCH);    // 8 x 32 x 4
        gemm3<<<g, 128, SMEM_REQ>>>(Phi, Plo, VThi, VTlo,
                                    SLEN, SLEN, NTOK,
                                    (long long)SLEN * SLEN, (long long)SLEN,
                                    (long long)SLEN * DIN,
                                    out, nullptr, nullptr, DIN, 0, 3);
    }
}

// round 9
// speedup vs baseline: 1.2330x; 1.1295x over previous
#include <cuda_runtime.h>
#include <cuda_bf16.h>
#include <cuda_fp16.h>
#include <cstdint>
#include <cstddef>

typedef __nv_bfloat16 bf16;
typedef __half fp16;

#define BATCH 4
#define SLEN  2048
#define DIN   1024
#define NTOK  (BATCH*SLEN)

// bf16 3-pass GEMM tiles: BM=64, BN=128, BK=64 -> stage 48KB, 2 CTAs/SM
#define BM 64
#define BN 128
#define BK 64
#define A_BYTES (64*128)
#define B_BYTES (128*128)
#define STAGE_BYTES (2*A_BYTES + 2*B_BYTES)   // 48KB
#define SM_A_HI 0
#define SM_A_LO (A_BYTES)
#define SM_B_HI (2*A_BYTES)
#define SM_B_LO (2*A_BYTES + B_BYTES)
#define SMEM_REQ (1024 + 2*STAGE_BYTES)

// fp16 2-pass GEMM: A split + B single -> stage 32KB, 3 CTAs/SM
#define STAGE2_BYTES (2*A_BYTES + B_BYTES)    // 32KB
#define SM2_A_HI 0
#define SM2_A_LO (A_BYTES)
#define SM2_B    (2*A_BYTES)
#define SMEM2_REQ (1024 + 2*STAGE2_BYTES)

// ---------------- scratch (device globals; no allocs allowed) ----------------
__device__ bf16 g_Xhi[(size_t)NTOK*DIN];
__device__ bf16 g_Xlo[(size_t)NTOK*DIN];
__device__ bf16 g_WThi[3][(size_t)DIN*DIN];   // W^T split; [0],[1] contiguous for merged QK
__device__ bf16 g_WTlo[3][(size_t)DIN*DIN];
__device__ fp16 g_QKhi[(size_t)NTOK*2*DIN];   // fp16 pair: cols 0..1023=Q, 1024..2047=K
__device__ fp16 g_QKlo[(size_t)NTOK*2*DIN];
__device__ fp16 g_VThi[(size_t)DIN*NTOK];     // V^T single fp16: [e][b*S+s]
__device__ float g_S[(size_t)BATCH*SLEN*SLEN];    // raw scores (unscaled)
__device__ fp16 g_Phi[(size_t)BATCH*SLEN*SLEN];
__device__ fp16 g_Plo[(size_t)BATCH*SLEN*SLEN];

// ---------------- helpers ----------------
__device__ __forceinline__ uint32_t smem_u32(const void* p) {
    return (uint32_t)__cvta_generic_to_shared(p);
}
#define CP_COMMIT() asm volatile("cp.async.commit_group;\n" ::: "memory")
#define CP_WAIT1()  asm volatile("cp.async.wait_group 1;\n" ::: "memory")
#define CP_WAIT0()  asm volatile("cp.async.wait_group 0;\n" ::: "memory")

__device__ __forceinline__ void ldsm4(uint32_t* r, uint32_t addr) {
    asm volatile("ldmatrix.sync.aligned.m8n8.x4.shared.b16 {%0,%1,%2,%3}, [%4];"
        : "=r"(r[0]), "=r"(r[1]), "=r"(r[2]), "=r"(r[3]) : "r"(addr));
}
__device__ __forceinline__ void mma_bf16(float* d, const uint32_t* a, const uint32_t* b) {
    asm volatile(
        "mma.sync.aligned.m16n8k16.row.col.f32.bf16.bf16.f32 "
        "{%0,%1,%2,%3}, {%4,%5,%6,%7}, {%8,%9}, {%0,%1,%2,%3};"
        : "+f"(d[0]), "+f"(d[1]), "+f"(d[2]), "+f"(d[3])
        : "r"(a[0]), "r"(a[1]), "r"(a[2]), "r"(a[3]), "r"(b[0]), "r"(b[1]));
}
__device__ __forceinline__ void mma_f16(float* d, const uint32_t* a, const uint32_t* b) {
    asm volatile(
        "mma.sync.aligned.m16n8k16.row.col.f32.f16.f16.f32 "
        "{%0,%1,%2,%3}, {%4,%5,%6,%7}, {%8,%9}, {%0,%1,%2,%3};"
        : "+f"(d[0]), "+f"(d[1]), "+f"(d[2]), "+f"(d[3])
        : "r"(a[0]), "r"(a[1]), "r"(a[2]), "r"(a[3]), "r"(b[0]), "r"(b[1]));
}

// cp.async a [ROWS x 64 elem] tile (128B rows, 2B elems) into swizzled smem; 128 thr
template<int ROWS, typename T>
__device__ __forceinline__ void load_tile(const T* __restrict__ g, int ld,
                                          int row0, int k0, uint32_t sdst, int tid)
{
#pragma unroll
    for (int c = tid; c < ROWS * 8; c += 128) {
        int r = c >> 3, col = c & 7;
        const void* src = (const void*)(g + (size_t)(row0 + r) * ld + k0 + col * 8);
        uint32_t dst = sdst + ((uint32_t)r << 7) + ((uint32_t)(col ^ (r & 7)) << 4);
        asm volatile("cp.async.cg.shared.global [%0], [%1], 16;\n" :: "r"(dst), "l"(src));
    }
}

// ---------------------------------------------------------------------------
// bf16 3-pass GEMM (projections): D = Ahi*Bhi + Ahi*Blo + Alo*Bhi
// mode 1: fp16 pair output; mode 2: fp16 single (hi) output
// ---------------------------------------------------------------------------
__global__ void __launch_bounds__(128)
gemm3(const bf16* __restrict__ Ahi, const bf16* __restrict__ Alo,
      const bf16* __restrict__ Bhi, const bf16* __restrict__ Blo,
      int K, int lda, int ldb,
      fp16* __restrict__ Chi, fp16* __restrict__ Clo,
      int ldc, int mode)
{
    const int bx = blockIdx.x, by = blockIdx.y;
    const int m0 = by * BM, n0 = bx * BN;
    const int nit = K / BK;

    extern __shared__ char smem_raw[];
    const uint32_t sbase = (smem_u32(smem_raw) + 1023u) & ~1023u;

    const int tid = threadIdx.x;
    const int wid = tid >> 5, lid = tid & 31;
    const int warp_m = wid >> 1;
    const int warp_n = wid & 1;

    float acc[2][8][4];
#pragma unroll
    for (int i = 0; i < 2; i++)
#pragma unroll
        for (int j = 0; j < 8; j++)
#pragma unroll
            for (int q = 0; q < 4; q++) acc[i][j][q] = 0.0f;

    const int a_row_base = warp_m * 32 + (lid & 15);
    const int a_chalf = lid >> 4;
    const int b_row_base = warp_n * 64 + (lid >> 4) * 8 + (lid & 7);
    const int b_chalf = (lid >> 3) & 1;

    load_tile<BM>(Ahi, lda, m0, 0, sbase + SM_A_HI, tid);
    load_tile<BM>(Alo, lda, m0, 0, sbase + SM_A_LO, tid);
    load_tile<BN>(Bhi, ldb, n0, 0, sbase + SM_B_HI, tid);
    load_tile<BN>(Blo, ldb, n0, 0, sbase + SM_B_LO, tid);
    CP_COMMIT();

    uint32_t ah[2][2][4], al[2][2][4];
    uint32_t bh[2][4][4], bl[2][4][4];

    for (int it = 0; it < nit; it++) {
        const int p = it & 1;
        if (it + 1 < nit) {
            const uint32_t sb = sbase + (p ^ 1) * STAGE_BYTES;
            const int k0 = (it + 1) * BK;
            load_tile<BM>(Ahi, lda, m0, k0, sb + SM_A_HI, tid);
            load_tile<BM>(Alo, lda, m0, k0, sb + SM_A_LO, tid);
            load_tile<BN>(Bhi, ldb, n0, k0, sb + SM_B_HI, tid);
            load_tile<BN>(Blo, ldb, n0, k0, sb + SM_B_LO, tid);
            CP_COMMIT();
            CP_WAIT1();
        } else {
            CP_WAIT0();
        }
        __syncthreads();

        const uint32_t sb = sbase + p * STAGE_BYTES;

#pragma unroll
        for (int im = 0; im < 2; im++) {
            const int row = a_row_base + im * 16;
            const uint32_t off = ((uint32_t)row << 7) + ((uint32_t)(a_chalf ^ (row & 7)) << 4);
            ldsm4(ah[0][im], sb + SM_A_HI + off);
            ldsm4(al[0][im], sb + SM_A_LO + off);
        }
#pragma unroll
        for (int jn = 0; jn < 4; jn++) {
            const int n = b_row_base + jn * 16;
            const uint32_t off = ((uint32_t)n << 7) + ((uint32_t)(b_chalf ^ (n & 7)) << 4);
            ldsm4(bh[0][jn], sb + SM_B_HI + off);
            ldsm4(bl[0][jn], sb + SM_B_LO + off);
        }

#pragma unroll
        for (int kk = 0; kk < 4; kk++) {
            const int cur = kk & 1, nxt = cur ^ 1;
            if (kk < 3) {
#pragma unroll
                for (int im = 0; im < 2; im++) {
                    const int row = a_row_base + im * 16;
                    const int c16 = (kk + 1) * 2 + a_chalf;
                    const uint32_t off = ((uint32_t)row << 7) + ((uint32_t)(c16 ^ (row & 7)) << 4);
                    ldsm4(ah[nxt][im], sb + SM_A_HI + off);
                    ldsm4(al[nxt][im], sb + SM_A_LO + off);
                }
#pragma unroll
                for (int jn = 0; jn < 4; jn++) {
                    const int n = b_row_base + jn * 16;
                    const int c16 = (kk + 1) * 2 + b_chalf;
                    const uint32_t off = ((uint32_t)n << 7) + ((uint32_t)(c16 ^ (n & 7)) << 4);
                    ldsm4(bh[nxt][jn], sb + SM_B_HI + off);
                    ldsm4(bl[nxt][jn], sb + SM_B_LO + off);
                }
            }
#pragma unroll
            for (int jn = 0; jn < 4; jn++) {
#pragma unroll
                for (int im = 0; im < 2; im++) {
#pragma unroll
                    for (int h = 0; h < 2; h++) {
                        float* d = acc[im][jn * 2 + h];
                        mma_bf16(d, ah[cur][im], bh[cur][jn] + 2 * h);
                        mma_bf16(d, ah[cur][im], bl[cur][jn] + 2 * h);
                        mma_bf16(d, al[cur][im], bh[cur][jn] + 2 * h);
                    }
                }
            }
        }
        __syncthreads();
    }

    // epilogue: fp16 pair (mode 1) or fp16 single (mode 2)
    const int tq = lid >> 2;
    const int tr = lid & 3;
#pragma unroll
    for (int im = 0; im < 2; im++) {
#pragma unroll
        for (int j = 0; j < 8; j++) {
            const int r0 = m0 + warp_m * 32 + im * 16 + tq;
            const int c0 = n0 + warp_n * 64 + j * 8 + tr * 2;
            const float* d = acc[im][j];
#pragma unroll
            for (int rr = 0; rr < 2; rr++) {
                float va = d[2 * rr], vb = d[2 * rr + 1];
                fp16 ha = __float2half_rn(va);
                fp16 hb = __float2half_rn(vb);
                __half2 hv; hv.x = ha; hv.y = hb;
                const size_t o = (size_t)(r0 + 8 * rr) * ldc + c0;
                *(uint32_t*)(Chi + o) = *(uint32_t*)&hv;
                if (mode == 1) {
                    __half2 lv;
                    lv.x = __float2half_rn(va - __half2float(ha));
                    lv.y = __float2half_rn(vb - __half2float(hb));
                    *(uint32_t*)(Clo + o) = *(uint32_t*)&lv;
                }
            }
        }
    }
}

// ---------------------------------------------------------------------------
// fp16 2-pass GEMM: D = (Ahi + Alo) * B   (A split fp16 pair, B single fp16)
// causal 1: skip tiles above diagonal, full K (scores)
// causal 3: kEnd=(by+1)*BM + load-balance remap (PV)
// fp32 output.
// ---------------------------------------------------------------------------
__global__ void __launch_bounds__(128, 3)
gemm2h(const fp16* __restrict__ Ahi, const fp16* __restrict__ Alo,
       const fp16* __restrict__ B,
       int K, int lda, int ldb,
       long long sAz, long long sBz, long long sCz,
       float* __restrict__ Cf, int ldc, int causal)
{
    const int bx = blockIdx.x, z = blockIdx.z;
    int by = blockIdx.y;
    if (causal == 3) {
        const int n = gridDim.y;
        by = (by & 1) ? (n - 1 - (by >> 1)) : (by >> 1);
    }
    const int m0 = by * BM, n0 = bx * BN;
    if (causal == 1 && n0 > m0 + (BM - 1)) return;

    const int kEnd = (causal == 3) ? (by + 1) * BM : K;
    const int nit = kEnd / BK;

    const fp16* Ah = Ahi + (size_t)z * sAz;
    const fp16* Al = Alo + (size_t)z * sAz;
    const fp16* Bp = B   + (size_t)z * sBz;

    extern __shared__ char smem_raw[];
    const uint32_t sbase = (smem_u32(smem_raw) + 1023u) & ~1023u;

    const int tid = threadIdx.x;
    const int wid = tid >> 5, lid = tid & 31;
    const int warp_m = wid >> 1;
    const int warp_n = wid & 1;

    float acc[2][8][4];
#pragma unroll
    for (int i = 0; i < 2; i++)
#pragma unroll
        for (int j = 0; j < 8; j++)
#pragma unroll
            for (int q = 0; q < 4; q++) acc[i][j][q] = 0.0f;

    const int a_row_base = warp_m * 32 + (lid & 15);
    const int a_chalf = lid >> 4;
    const int b_row_base = warp_n * 64 + (lid >> 4) * 8 + (lid & 7);
    const int b_chalf = (lid >> 3) & 1;

    load_tile<BM>(Ah, lda, m0, 0, sbase + SM2_A_HI, tid);
    load_tile<BM>(Al, lda, m0, 0, sbase + SM2_A_LO, tid);
    load_tile<BN>(Bp, ldb, n0, 0, sbase + SM2_B, tid);
    CP_COMMIT();

    uint32_t ah[2][2][4], al[2][2][4];
    uint32_t bh[2][4][4];

    for (int it = 0; it < nit; it++) {
        const int p = it & 1;
        if (it + 1 < nit) {
            const uint32_t sb = sbase + (p ^ 1) * STAGE2_BYTES;
            const int k0 = (it + 1) * BK;
            load_tile<BM>(Ah, lda, m0, k0, sb + SM2_A_HI, tid);
            load_tile<BM>(Al, lda, m0, k0, sb + SM2_A_LO, tid);
            load_tile<BN>(Bp, ldb, n0, k0, sb + SM2_B, tid);
            CP_COMMIT();
            CP_WAIT1();
        } else {
            CP_WAIT0();
        }
        __syncthreads();

        const uint32_t sb = sbase + p * STAGE2_BYTES;

#pragma unroll
        for (int im = 0; im < 2; im++) {
            const int row = a_row_base + im * 16;
            const uint32_t off = ((uint32_t)row << 7) + ((uint32_t)(a_chalf ^ (row & 7)) << 4);
            ldsm4(ah[0][im], sb + SM2_A_HI + off);
            ldsm4(al[0][im], sb + SM2_A_LO + off);
        }
#pragma unroll
        for (int jn = 0; jn < 4; jn++) {
            const int n = b_row_base + jn * 16;
            const uint32_t off = ((uint32_t)n << 7) + ((uint32_t)(b_chalf ^ (n & 7)) << 4);
            ldsm4(bh[0][jn], sb + SM2_B + off);
        }

#pragma unroll
        for (int kk = 0; kk < 4; kk++) {
            const int cur = kk & 1, nxt = cur ^ 1;
            if (kk < 3) {
#pragma unroll
                for (int im = 0; im < 2; im++) {
                    const int row = a_row_base + im * 16;
                    const int c16 = (kk + 1) * 2 + a_chalf;
                    const uint32_t off = ((uint32_t)row << 7) + ((uint32_t)(c16 ^ (row & 7)) << 4);
                    ldsm4(ah[nxt][im], sb + SM2_A_HI + off);
                    ldsm4(al[nxt][im], sb + SM2_A_LO + off);
                }
#pragma unroll
                for (int jn = 0; jn < 4; jn++) {
                    const int n = b_row_base + jn * 16;
                    const int c16 = (kk + 1) * 2 + b_chalf;
                    const uint32_t off = ((uint32_t)n << 7) + ((uint32_t)(c16 ^ (n & 7)) << 4);
                    ldsm4(bh[nxt][jn], sb + SM2_B + off);
                }
            }
#pragma unroll
            for (int jn = 0; jn < 4; jn++) {
#pragma unroll
                for (int im = 0; im < 2; im++) {
#pragma unroll
                    for (int h = 0; h < 2; h++) {
                        float* d = acc[im][jn * 2 + h];
                        mma_f16(d, ah[cur][im], bh[cur][jn] + 2 * h);
                        mma_f16(d, al[cur][im], bh[cur][jn] + 2 * h);
                    }
                }
            }
        }
        __syncthreads();
    }

    const int tq = lid >> 2;
    const int tr = lid & 3;
    const size_t cbase = (size_t)z * (size_t)sCz;
#pragma unroll
    for (int im = 0; im < 2; im++) {
#pragma unroll
        for (int j = 0; j < 8; j++) {
            const int r0 = m0 + warp_m * 32 + im * 16 + tq;
            const int c0 = n0 + warp_n * 64 + j * 8 + tr * 2;
            const float* d = acc[im][j];
            *(float2*)(Cf + cbase + (size_t)r0 * ldc + c0)       = make_float2(d[0], d[1]);
            *(float2*)(Cf + cbase + (size_t)(r0 + 8) * ldc + c0) = make_float2(d[2], d[3]);
        }
    }
}

// ---------------------------------------------------------------------------
__global__ void __launch_bounds__(256)
split_f32(const float* __restrict__ x, bf16* __restrict__ hi, bf16* __restrict__ lo, int n4)
{
    int i = blockIdx.x * 256 + threadIdx.x;
    if (i >= n4) return;
    float4 v = ((const float4*)x)[i];
    float f[4] = {v.x, v.y, v.z, v.w};
    bf16 h[4]; bf16 l[4];
#pragma unroll
    for (int j = 0; j < 4; j++) {
        h[j] = __float2bfloat16(f[j]);
        l[j] = __float2bfloat16(f[j] - __bfloat162float(h[j]));
    }
    ((uint2*)hi)[i] = *(uint2*)h;
    ((uint2*)lo)[i] = *(uint2*)l;
}

// ---------------------------------------------------------------------------
__global__ void __launch_bounds__(256)
transpose_split3(const float* __restrict__ W0, const float* __restrict__ W1,
                 const float* __restrict__ W2, bf16* __restrict__ Thi,
                 bf16* __restrict__ Tlo)
{
    const int zz = blockIdx.z;
    const float* W = (zz == 0) ? W0 : (zz == 1) ? W1 : W2;
    const size_t zoff = (size_t)zz * DIN * DIN;

    __shared__ float t[32][33];
    const int bx = blockIdx.x * 32, by = blockIdx.y * 32;
    const int x = threadIdx.x, y = threadIdx.y;
#pragma unroll
    for (int i = 0; i < 32; i += 8)
        t[y + i][x] = W[(size_t)(by + y + i) * DIN + bx + x];
    __syncthreads();
#pragma unroll
    for (int i = 0; i < 32; i += 8) {
        float v = t[x][y + i];
        bf16 h = __float2bfloat16(v);
        bf16 l = __float2bfloat16(v - __bfloat162float(h));
        Thi[zoff + (size_t)(bx + y + i) * DIN + by + x] = h;
        Tlo[zoff + (size_t)(bx + y + i) * DIN + by + x] = l;
    }
}

// ---------------------------------------------------------------------------
// Softmax over k<=q of scale*S, emit fp16 pair P, zero-pad to 64 boundary
// ---------------------------------------------------------------------------
__global__ void __launch_bounds__(256)
softmax_split(const float* __restrict__ S, fp16* __restrict__ Phi, fp16* __restrict__ Plo,
              float scale)
{
    const int row = blockIdx.x;
    const int q = row & (SLEN - 1);
    const float* p = S + (size_t)row * SLEN;
    const int L = q + 1;
    const int t = threadIdx.x;

    float v[8];
    float mx = -INFINITY;
#pragma unroll
    for (int i = 0; i < 8; i++) {
        int idx = t + i * 256;
        v[i] = (idx < L) ? p[idx] * scale : -INFINITY;
        mx = fmaxf(mx, v[i]);
    }

    __shared__ float redm[8];
    __shared__ float reds[8];

#pragma unroll
    for (int o = 16; o; o >>= 1) mx = fmaxf(mx, __shfl_xor_sync(0xFFFFFFFFu, mx, o));
    if ((t & 31) == 0) redm[t >> 5] = mx;
    __syncthreads();
    float m = redm[0];
#pragma unroll
    for (int i = 1; i < 8; i++) m = fmaxf(m, redm[i]);

    float s = 0.0f;
#pragma unroll
    for (int i = 0; i < 8; i++) {
        float e = __expf(v[i] - m);
        v[i] = e;
        s += e;
    }
#pragma unroll
    for (int o = 16; o; o >>= 1) s += __shfl_xor_sync(0xFFFFFFFFu, s, o);
    if ((t & 31) == 0) reds[t >> 5] = s;
    __syncthreads();
    float tot = 0.0f;
#pragma unroll
    for (int i = 0; i < 8; i++) tot += reds[i];
    const float inv = 1.0f / tot;

    fp16* ph = Phi + (size_t)row * SLEN;
    fp16* pl = Plo + (size_t)row * SLEN;
    const int pad = (L + 63) & ~63;
#pragma unroll
    for (int i = 0; i < 8; i++) {
        int idx = t + i * 256;
        if (idx < L) {
            float w = v[i] * inv;
            fp16 h = __float2half_rn(w);
            ph[idx] = h;
            pl[idx] = __float2half_rn(w - __half2float(h));
        } else if (idx < pad) {
            ph[idx] = __float2half_rn(0.0f);
            pl[idx] = __float2half_rn(0.0f);
        }
    }
}

// ---------------------------------------------------------------------------
extern "C" void kernel_launch(void* const* d_in, const int* in_sizes, int n_in,
                              void* d_out, int out_size)
{
    const float* x  = (const float*)d_in[0];
    const float* Wq = (const float*)d_in[1];
    const float* Wk = (const float*)d_in[2];
    const float* Wv = (const float*)d_in[3];
    float* out = (float*)d_out;
    (void)in_sizes; (void)n_in; (void)out_size;

    cudaFuncSetAttribute(gemm3, cudaFuncAttributeMaxDynamicSharedMemorySize, SMEM_REQ);
    cudaFuncSetAttribute(gemm2h, cudaFuncAttributeMaxDynamicSharedMemorySize, SMEM2_REQ);

    bf16 *Xhi, *Xlo, *WThi, *WTlo;
    fp16 *QKhi, *QKlo, *VThi, *Phi, *Plo;
    float *Sp;
    cudaGetSymbolAddress((void**)&Xhi, g_Xhi);
    cudaGetSymbolAddress((void**)&Xlo, g_Xlo);
    cudaGetSymbolAddress((void**)&WThi, g_WThi);
    cudaGetSymbolAddress((void**)&WTlo, g_WTlo);
    cudaGetSymbolAddress((void**)&QKhi, g_QKhi);
    cudaGetSymbolAddress((void**)&QKlo, g_QKlo);
    cudaGetSymbolAddress((void**)&VThi, g_VThi);
    cudaGetSymbolAddress((void**)&Sp, g_S);
    cudaGetSymbolAddress((void**)&Phi, g_Phi);
    cudaGetSymbolAddress((void**)&Plo, g_Plo);

    const size_t WSTRIDE = (size_t)DIN * DIN;

    // 1) split x into bf16 pair
    split_f32<<<(NTOK * DIN / 4) / 256, 256>>>(x, Xhi, Xlo, NTOK * DIN / 4);

    // 2) transpose + split all three weights (bf16 pair)
    {
        dim3 g(DIN / 32, DIN / 32, 3), b(32, 8);
        transpose_split3<<<g, b>>>(Wq, Wk, Wv, WThi, WTlo);
    }

    // 3) merged QK projection (bf16 3-pass) -> fp16 pair, interleaved ldc=2048
    {
        dim3 g(2 * DIN / BN, NTOK / BM, 1);   // 16 x 128
        gemm3<<<g, 128, SMEM_REQ>>>(Xhi, Xlo, WThi, WTlo,
                                    DIN, DIN, DIN,
                                    QKhi, QKlo, 2 * DIN, 1);
    }

    // 4) V^T projection (bf16 3-pass) -> fp16 single
    {
        dim3 g(NTOK / BN, DIN / BM, 1);   // 64 x 16
        gemm3<<<g, 128, SMEM_REQ>>>(WThi + 2 * WSTRIDE, WTlo + 2 * WSTRIDE, Xhi, Xlo,
                                    DIN, DIN, DIN,
                                    VThi, nullptr, NTOK, 2);
    }

    // 5) scores (fp16 2-pass): A = Q pair, B = K hi (cols 1024..2047), causal skip
    {
        dim3 g(SLEN / BN, SLEN / BM, BATCH);   // 16 x 32 x 4
        gemm2h<<<g, 128, SMEM2_REQ>>>(QKhi, QKlo, QKhi + DIN,
                                      DIN, 2 * DIN, 2 * DIN,
                                      (long long)SLEN * 2 * DIN, (long long)SLEN * 2 * DIN,
                                      (long long)SLEN * SLEN,
                                      Sp, SLEN, 1);
    }

    // 6) softmax -> fp16 pair P
    softmax_split<<<BATCH * SLEN, 256>>>(Sp, Phi, Plo, 0.03125f);

    // 7) PV (fp16 2-pass): A = P pair, B = V^T single, k-bound + remap
    {
        dim3 g(DIN / BN, SLEN / BM, BATCH);    // 8 x 32 x 4
        gemm2h<<<g, 128, SMEM2_REQ>>>(Phi, Plo, VThi,
                                      SLEN, SLEN, NTOK,
                                      (long long)SLEN * SLEN, (long long)SLEN,
                                      (long long)SLEN * DIN,
                                      out, DIN, 3);
    }
}

// round 10
// speedup vs baseline: 1.6135x; 1.3086x over previous
#include <cuda_runtime.h>
#include <cuda_fp16.h>
#include <cstdint>
#include <cstddef>

typedef __half fp16;

#define BATCH 4
#define SLEN  2048
#define DIN   1024
#define NTOK  (BATCH*SLEN)

// fp16 2-pass GEMM tiles: BM=64, BN=128, BK=64 -> stage 32KB, 3 CTAs/SM
#define BM 64
#define BN 128
#define BK 64
#define A_BYTES (64*128)
#define B_BYTES (128*128)
#define STAGE2_BYTES (2*A_BYTES + B_BYTES)    // 32KB
#define SM2_A_HI 0
#define SM2_A_LO (A_BYTES)
#define SM2_B    (2*A_BYTES)
#define SMEM2_REQ (1024 + 2*STAGE2_BYTES)

// ---------------- scratch (device globals; no allocs allowed) ----------------
__device__ fp16 g_Xhi[(size_t)NTOK*DIN];      // X fp16 pair (hi doubles as B-single)
__device__ fp16 g_Xlo[(size_t)NTOK*DIN];
__device__ fp16 g_WThi[3][(size_t)DIN*DIN];   // W^T fp16 pair; [0],[1] contiguous = QK B
__device__ fp16 g_WTlo[3][(size_t)DIN*DIN];
__device__ fp16 g_QKhi[(size_t)NTOK*2*DIN];   // fp16 pair: cols 0..1023=Q, 1024..2047=K
__device__ fp16 g_QKlo[(size_t)NTOK*2*DIN];
__device__ fp16 g_VThi[(size_t)DIN*NTOK];     // V^T single fp16: [e][b*S+s]
__device__ float g_S[(size_t)BATCH*SLEN*SLEN];    // raw scores (unscaled)
__device__ fp16 g_Phi[(size_t)BATCH*SLEN*SLEN];
__device__ fp16 g_Plo[(size_t)BATCH*SLEN*SLEN];

// ---------------- helpers ----------------
__device__ __forceinline__ uint32_t smem_u32(const void* p) {
    return (uint32_t)__cvta_generic_to_shared(p);
}
#define CP_COMMIT() asm volatile("cp.async.commit_group;\n" ::: "memory")
#define CP_WAIT1()  asm volatile("cp.async.wait_group 1;\n" ::: "memory")
#define CP_WAIT0()  asm volatile("cp.async.wait_group 0;\n" ::: "memory")

__device__ __forceinline__ void ldsm4(uint32_t* r, uint32_t addr) {
    asm volatile("ldmatrix.sync.aligned.m8n8.x4.shared.b16 {%0,%1,%2,%3}, [%4];"
        : "=r"(r[0]), "=r"(r[1]), "=r"(r[2]), "=r"(r[3]) : "r"(addr));
}
__device__ __forceinline__ void mma_f16(float* d, const uint32_t* a, const uint32_t* b) {
    asm volatile(
        "mma.sync.aligned.m16n8k16.row.col.f32.f16.f16.f32 "
        "{%0,%1,%2,%3}, {%4,%5,%6,%7}, {%8,%9}, {%0,%1,%2,%3};"
        : "+f"(d[0]), "+f"(d[1]), "+f"(d[2]), "+f"(d[3])
        : "r"(a[0]), "r"(a[1]), "r"(a[2]), "r"(a[3]), "r"(b[0]), "r"(b[1]));
}

// cp.async a [ROWS x 64 fp16] tile (128B rows) into swizzled smem; 128 threads
template<int ROWS>
__device__ __forceinline__ void load_tile(const fp16* __restrict__ g, int ld,
                                          int row0, int k0, uint32_t sdst, int tid)
{
#pragma unroll
    for (int c = tid; c < ROWS * 8; c += 128) {
        int r = c >> 3, col = c & 7;
        const void* src = (const void*)(g + (size_t)(row0 + r) * ld + k0 + col * 8);
        uint32_t dst = sdst + ((uint32_t)r << 7) + ((uint32_t)(col ^ (r & 7)) << 4);
        asm volatile("cp.async.cg.shared.global [%0], [%1], 16;\n" :: "r"(dst), "l"(src));
    }
}

// ---------------------------------------------------------------------------
// fp16 2-pass GEMM: D = (Ahi + Alo) * B   (A split fp16 pair, B single fp16)
// mode 0: fp32 output; mode 1: fp16 pair output; mode 2: fp16 single output
// causal 0: none; 1: skip tiles above diagonal (scores);
//        3: kEnd=(by+1)*BM + load-balance remap of by (PV)
// 128 threads, warps 2m x 2n, warp tile 32x64; reg-level fragment double-buffer.
// ---------------------------------------------------------------------------
__global__ void __launch_bounds__(128, 3)
gemm2h(const fp16* __restrict__ Ahi, const fp16* __restrict__ Alo,
       const fp16* __restrict__ B,
       int K, int lda, int ldb,
       long long sAz, long long sBz, long long sCz,
       float* __restrict__ Cf, fp16* __restrict__ Chi, fp16* __restrict__ Clo,
       int ldc, int mode, int causal)
{
    const int bx = blockIdx.x, z = blockIdx.z;
    int by = blockIdx.y;
    if (causal == 3) {
        const int n = gridDim.y;
        by = (by & 1) ? (n - 1 - (by >> 1)) : (by >> 1);
    }
    const int m0 = by * BM, n0 = bx * BN;
    if (causal == 1 && n0 > m0 + (BM - 1)) return;

    const int kEnd = (causal == 3) ? (by + 1) * BM : K;
    const int nit = kEnd / BK;

    const fp16* Ah = Ahi + (size_t)z * sAz;
    const fp16* Al = Alo + (size_t)z * sAz;
    const fp16* Bp = B   + (size_t)z * sBz;

    extern __shared__ char smem_raw[];
    const uint32_t sbase = (smem_u32(smem_raw) + 1023u) & ~1023u;

    const int tid = threadIdx.x;
    const int wid = tid >> 5, lid = tid & 31;
    const int warp_m = wid >> 1;
    const int warp_n = wid & 1;

    float acc[2][8][4];
#pragma unroll
    for (int i = 0; i < 2; i++)
#pragma unroll
        for (int j = 0; j < 8; j++)
#pragma unroll
            for (int q = 0; q < 4; q++) acc[i][j][q] = 0.0f;

    const int a_row_base = warp_m * 32 + (lid & 15);
    const int a_chalf = lid >> 4;
    const int b_row_base = warp_n * 64 + (lid >> 4) * 8 + (lid & 7);
    const int b_chalf = (lid >> 3) & 1;

    load_tile<BM>(Ah, lda, m0, 0, sbase + SM2_A_HI, tid);
    load_tile<BM>(Al, lda, m0, 0, sbase + SM2_A_LO, tid);
    load_tile<BN>(Bp, ldb, n0, 0, sbase + SM2_B, tid);
    CP_COMMIT();

    uint32_t ah[2][2][4], al[2][2][4];
    uint32_t bh[2][4][4];

    for (int it = 0; it < nit; it++) {
        const int p = it & 1;
        if (it + 1 < nit) {
            const uint32_t sb = sbase + (p ^ 1) * STAGE2_BYTES;
            const int k0 = (it + 1) * BK;
            load_tile<BM>(Ah, lda, m0, k0, sb + SM2_A_HI, tid);
            load_tile<BM>(Al, lda, m0, k0, sb + SM2_A_LO, tid);
            load_tile<BN>(Bp, ldb, n0, k0, sb + SM2_B, tid);
            CP_COMMIT();
            CP_WAIT1();
        } else {
            CP_WAIT0();
        }
        __syncthreads();

        const uint32_t sb = sbase + p * STAGE2_BYTES;

        // preload kk=0 fragments
#pragma unroll
        for (int im = 0; im < 2; im++) {
            const int row = a_row_base + im * 16;
            const uint32_t off = ((uint32_t)row << 7) + ((uint32_t)(a_chalf ^ (row & 7)) << 4);
            ldsm4(ah[0][im], sb + SM2_A_HI + off);
            ldsm4(al[0][im], sb + SM2_A_LO + off);
        }
#pragma unroll
        for (int jn = 0; jn < 4; jn++) {
            const int n = b_row_base + jn * 16;
            const uint32_t off = ((uint32_t)n << 7) + ((uint32_t)(b_chalf ^ (n & 7)) << 4);
            ldsm4(bh[0][jn], sb + SM2_B + off);
        }

#pragma unroll
        for (int kk = 0; kk < 4; kk++) {
            const int cur = kk & 1, nxt = cur ^ 1;
            if (kk < 3) {   // prefetch kk+1 fragments during kk's MMAs
#pragma unroll
                for (int im = 0; im < 2; im++) {
                    const int row = a_row_base + im * 16;
                    const int c16 = (kk + 1) * 2 + a_chalf;
                    const uint32_t off = ((uint32_t)row << 7) + ((uint32_t)(c16 ^ (row & 7)) << 4);
                    ldsm4(ah[nxt][im], sb + SM2_A_HI + off);
                    ldsm4(al[nxt][im], sb + SM2_A_LO + off);
                }
#pragma unroll
                for (int jn = 0; jn < 4; jn++) {
                    const int n = b_row_base + jn * 16;
                    const int c16 = (kk + 1) * 2 + b_chalf;
                    const uint32_t off = ((uint32_t)n << 7) + ((uint32_t)(c16 ^ (n & 7)) << 4);
                    ldsm4(bh[nxt][jn], sb + SM2_B + off);
                }
            }
#pragma unroll
            for (int jn = 0; jn < 4; jn++) {
#pragma unroll
                for (int im = 0; im < 2; im++) {
#pragma unroll
                    for (int h = 0; h < 2; h++) {
                        float* d = acc[im][jn * 2 + h];
                        mma_f16(d, ah[cur][im], bh[cur][jn] + 2 * h);
                        mma_f16(d, al[cur][im], bh[cur][jn] + 2 * h);
                    }
                }
            }
        }
        __syncthreads();
    }

    // epilogue
    const int tq = lid >> 2;
    const int tr = lid & 3;
    const size_t cbase = (size_t)z * (size_t)sCz;
#pragma unroll
    for (int im = 0; im < 2; im++) {
#pragma unroll
        for (int j = 0; j < 8; j++) {
            const int r0 = m0 + warp_m * 32 + im * 16 + tq;
            const int c0 = n0 + warp_n * 64 + j * 8 + tr * 2;
            const float* d = acc[im][j];
            if (mode == 0) {
                *(float2*)(Cf + cbase + (size_t)r0 * ldc + c0)       = make_float2(d[0], d[1]);
                *(float2*)(Cf + cbase + (size_t)(r0 + 8) * ldc + c0) = make_float2(d[2], d[3]);
            } else {
#pragma unroll
                for (int rr = 0; rr < 2; rr++) {
                    float va = d[2 * rr], vb = d[2 * rr + 1];
                    fp16 ha = __float2half_rn(va);
                    fp16 hb = __float2half_rn(vb);
                    __half2 hv; hv.x = ha; hv.y = hb;
                    const size_t o = cbase + (size_t)(r0 + 8 * rr) * ldc + c0;
                    *(uint32_t*)(Chi + o) = *(uint32_t*)&hv;
                    if (mode == 1) {
                        __half2 lv;
                        lv.x = __float2half_rn(va - __half2float(ha));
                        lv.y = __float2half_rn(vb - __half2float(hb));
                        *(uint32_t*)(Clo + o) = *(uint32_t*)&lv;
                    }
                }
            }
        }
    }
}

// ---------------------------------------------------------------------------
// fp32 -> fp16 (hi, lo) pair, elementwise (4 per thread)
// ---------------------------------------------------------------------------
__global__ void __launch_bounds__(256)
split_f32(const float* __restrict__ x, fp16* __restrict__ hi, fp16* __restrict__ lo, int n4)
{
    int i = blockIdx.x * 256 + threadIdx.x;
    if (i >= n4) return;
    float4 v = ((const float4*)x)[i];
    float f[4] = {v.x, v.y, v.z, v.w};
    fp16 h[4]; fp16 l[4];
#pragma unroll
    for (int j = 0; j < 4; j++) {
        h[j] = __float2half_rn(f[j]);
        l[j] = __float2half_rn(f[j] - __half2float(h[j]));
    }
    ((uint2*)hi)[i] = *(uint2*)h;
    ((uint2*)lo)[i] = *(uint2*)l;
}

// ---------------------------------------------------------------------------
// All three weights: W [DIN x DIN] fp32 -> W^T fp16 pair (z selects matrix)
// ---------------------------------------------------------------------------
__global__ void __launch_bounds__(256)
transpose_split3(const float* __restrict__ W0, const float* __restrict__ W1,
                 const float* __restrict__ W2, fp16* __restrict__ Thi,
                 fp16* __restrict__ Tlo)
{
    const int zz = blockIdx.z;
    const float* W = (zz == 0) ? W0 : (zz == 1) ? W1 : W2;
    const size_t zoff = (size_t)zz * DIN * DIN;

    __shared__ float t[32][33];
    const int bx = blockIdx.x * 32, by = blockIdx.y * 32;
    const int x = threadIdx.x, y = threadIdx.y;
#pragma unroll
    for (int i = 0; i < 32; i += 8)
        t[y + i][x] = W[(size_t)(by + y + i) * DIN + bx + x];
    __syncthreads();
#pragma unroll
    for (int i = 0; i < 32; i += 8) {
        float v = t[x][y + i];
        fp16 h = __float2half_rn(v);
        fp16 l = __float2half_rn(v - __half2float(h));
        Thi[zoff + (size_t)(bx + y + i) * DIN + by + x] = h;
        Tlo[zoff + (size_t)(bx + y + i) * DIN + by + x] = l;
    }
}

// ---------------------------------------------------------------------------
// Softmax over k<=q of scale*S, emit fp16 pair P, zero-pad to 64 boundary
// ---------------------------------------------------------------------------
__global__ void __launch_bounds__(256)
softmax_split(const float* __restrict__ S, fp16* __restrict__ Phi, fp16* __restrict__ Plo,
              float scale)
{
    const int row = blockIdx.x;
    const int q = row & (SLEN - 1);
    const float* p = S + (size_t)row * SLEN;
    const int L = q + 1;
    const int t = threadIdx.x;

    float v[8];
    float mx = -INFINITY;
#pragma unroll
    for (int i = 0; i < 8; i++) {
        int idx = t + i * 256;
        v[i] = (idx < L) ? p[idx] * scale : -INFINITY;
        mx = fmaxf(mx, v[i]);
    }

    __shared__ float redm[8];
    __shared__ float reds[8];

#pragma unroll
    for (int o = 16; o; o >>= 1) mx = fmaxf(mx, __shfl_xor_sync(0xFFFFFFFFu, mx, o));
    if ((t & 31) == 0) redm[t >> 5] = mx;
    __syncthreads();
    float m = redm[0];
#pragma unroll
    for (int i = 1; i < 8; i++) m = fmaxf(m, redm[i]);

    float s = 0.0f;
#pragma unroll
    for (int i = 0; i < 8; i++) {
        float e = __expf(v[i] - m);
        v[i] = e;
        s += e;
    }
#pragma unroll
    for (int o = 16; o; o >>= 1) s += __shfl_xor_sync(0xFFFFFFFFu, s, o);
    if ((t & 31) == 0) reds[t >> 5] = s;
    __syncthreads();
    float tot = 0.0f;
#pragma unroll
    for (int i = 0; i < 8; i++) tot += reds[i];
    const float inv = 1.0f / tot;

    fp16* ph = Phi + (size_t)row * SLEN;
    fp16* pl = Plo + (size_t)row * SLEN;
    const int pad = (L + 63) & ~63;
#pragma unroll
    for (int i = 0; i < 8; i++) {
        int idx = t + i * 256;
        if (idx < L) {
            float w = v[i] * inv;
            fp16 h = __float2half_rn(w);
            ph[idx] = h;
            pl[idx] = __float2half_rn(w - __half2float(h));
        } else if (idx < pad) {
            ph[idx] = __float2half_rn(0.0f);
            pl[idx] = __float2half_rn(0.0f);
        }
    }
}

// ---------------------------------------------------------------------------
extern "C" void kernel_launch(void* const* d_in, const int* in_sizes, int n_in,
                              void* d_out, int out_size)
{
    const float* x  = (const float*)d_in[0];
    const float* Wq = (const float*)d_in[1];
    const float* Wk = (const float*)d_in[2];
    const float* Wv = (const float*)d_in[3];
    float* out = (float*)d_out;
    (void)in_sizes; (void)n_in; (void)out_size;

    cudaFuncSetAttribute(gemm2h, cudaFuncAttributeMaxDynamicSharedMemorySize, SMEM2_REQ);

    fp16 *Xhi, *Xlo, *WThi, *WTlo, *QKhi, *QKlo, *VThi, *Phi, *Plo;
    float *Sp;
    cudaGetSymbolAddress((void**)&Xhi, g_Xhi);
    cudaGetSymbolAddress((void**)&Xlo, g_Xlo);
    cudaGetSymbolAddress((void**)&WThi, g_WThi);
    cudaGetSymbolAddress((void**)&WTlo, g_WTlo);
    cudaGetSymbolAddress((void**)&QKhi, g_QKhi);
    cudaGetSymbolAddress((void**)&QKlo, g_QKlo);
    cudaGetSymbolAddress((void**)&VThi, g_VThi);
    cudaGetSymbolAddress((void**)&Sp, g_S);
    cudaGetSymbolAddress((void**)&Phi, g_Phi);
    cudaGetSymbolAddress((void**)&Plo, g_Plo);

    const size_t WSTRIDE = (size_t)DIN * DIN;

    // 1) split x into fp16 pair (hi doubles as the quantized B for V proj)
    split_f32<<<(NTOK * DIN / 4) / 256, 256>>>(x, Xhi, Xlo, NTOK * DIN / 4);

    // 2) transpose + split all three weights into fp16 pairs
    {
        dim3 g(DIN / 32, DIN / 32, 3), b(32, 8);
        transpose_split3<<<g, b>>>(Wq, Wk, Wv, WThi, WTlo);
    }

    // 3) merged QK projection (2-pass): A = X pair, B = [Wq^T;Wk^T] hi single
    {
        dim3 g(2 * DIN / BN, NTOK / BM, 1);   // 16 x 128
        gemm2h<<<g, 128, SMEM2_REQ>>>(Xhi, Xlo, WThi,
                                      DIN, DIN, DIN, 0, 0, 0,
                                      nullptr, QKhi, QKlo, 2 * DIN, 1, 0);
    }

    // 4) V^T projection (2-pass): A = Wv^T pair, B = X hi single -> fp16 single
    {
        dim3 g(NTOK / BN, DIN / BM, 1);   // 64 x 16
        gemm2h<<<g, 128, SMEM2_REQ>>>(WThi + 2 * WSTRIDE, WTlo + 2 * WSTRIDE, Xhi,
                                      DIN, DIN, DIN, 0, 0, 0,
                                      nullptr, VThi, nullptr, NTOK, 2, 0);
    }

    // 5) scores (2-pass): A = Q pair, B = K hi (cols 1024..2047), causal skip
    {
        dim3 g(SLEN / BN, SLEN / BM, BATCH);   // 16 x 32 x 4
        gemm2h<<<g, 128, SMEM2_REQ>>>(QKhi, QKlo, QKhi + DIN,
                                      DIN, 2 * DIN, 2 * DIN,
                                      (long long)SLEN * 2 * DIN, (long long)SLEN * 2 * DIN,
                                      (long long)SLEN * SLEN,
                                      Sp, nullptr, nullptr, SLEN, 0, 1);
    }

    // 6) softmax -> fp16 pair P
    softmax_split<<<BATCH * SLEN, 256>>>(Sp, Phi, Plo, 0.03125f);

    // 7) PV (2-pass): A = P pair, B = V^T single, k-bound + remap
    {
        dim3 g(DIN / BN, SLEN / BM, BATCH);    // 8 x 32 x 4
        gemm2h<<<g, 128, SMEM2_REQ>>>(Phi, Plo, VThi,
                                      SLEN, SLEN, NTOK,
                                      (long long)SLEN * SLEN, (long long)SLEN,
                                      (long long)SLEN * DIN,
                                      out, nullptr, nullptr, DIN, 0, 3);
    }
}

// round 11
// speedup vs baseline: 1.9406x; 1.2027x over previous
#include <cuda_runtime.h>
#include <cuda_fp16.h>
#include <cstdint>
#include <cstddef>

typedef __half fp16;

#define BATCH 4
#define SLEN  2048
#define DIN   1024
#define NTOK  (BATCH*SLEN)

#define BM 64
#define BN 128
#define BK 64
#define A_BYTES (64*128)            // 8KB
#define B_BYTES (128*128)           // 16KB

// 2-pass: Ahi+Alo+B = 32KB/stage; 1-pass: Ahi+B = 24KB/stage
#define STAGE_T (2*A_BYTES + B_BYTES)
#define STAGE_O (A_BYTES + B_BYTES)
#define SMEM_T (1024 + 2*STAGE_T)
#define SMEM_O (1024 + 2*STAGE_O)

// ---------------- scratch (device globals; no allocs allowed) ----------------
__device__ fp16 g_Xhi[(size_t)NTOK*DIN];      // X fp16 pair (hi doubles as B-single)
__device__ fp16 g_Xlo[(size_t)NTOK*DIN];
__device__ fp16 g_WThi[3][(size_t)DIN*DIN];   // W^T fp16 pair; [0],[1] contiguous = QK B
__device__ fp16 g_WTlo[3][(size_t)DIN*DIN];
__device__ fp16 g_QK[(size_t)NTOK*2*DIN];     // fp16 single: cols 0..1023=Q, 1024..2047=K
__device__ fp16 g_VT[(size_t)DIN*NTOK];       // V^T single fp16: [e][b*S+s]
__device__ float g_S[(size_t)BATCH*SLEN*SLEN];    // raw scores (unscaled)
__device__ fp16 g_P[(size_t)BATCH*SLEN*SLEN];     // softmax weights, fp16 single

// ---------------- helpers ----------------
__device__ __forceinline__ uint32_t smem_u32(const void* p) {
    return (uint32_t)__cvta_generic_to_shared(p);
}
#define CP_COMMIT() asm volatile("cp.async.commit_group;\n" ::: "memory")
#define CP_WAIT1()  asm volatile("cp.async.wait_group 1;\n" ::: "memory")
#define CP_WAIT0()  asm volatile("cp.async.wait_group 0;\n" ::: "memory")

__device__ __forceinline__ void ldsm4(uint32_t* r, uint32_t addr) {
    asm volatile("ldmatrix.sync.aligned.m8n8.x4.shared.b16 {%0,%1,%2,%3}, [%4];"
        : "=r"(r[0]), "=r"(r[1]), "=r"(r[2]), "=r"(r[3]) : "r"(addr));
}
__device__ __forceinline__ void mma_f16(float* d, const uint32_t* a, const uint32_t* b) {
    asm volatile(
        "mma.sync.aligned.m16n8k16.row.col.f32.f16.f16.f32 "
        "{%0,%1,%2,%3}, {%4,%5,%6,%7}, {%8,%9}, {%0,%1,%2,%3};"
        : "+f"(d[0]), "+f"(d[1]), "+f"(d[2]), "+f"(d[3])
        : "r"(a[0]), "r"(a[1]), "r"(a[2]), "r"(a[3]), "r"(b[0]), "r"(b[1]));
}

// cp.async a [ROWS x 64 fp16] tile (128B rows) into swizzled smem; 128 threads
template<int ROWS>
__device__ __forceinline__ void load_tile(const fp16* __restrict__ g, int ld,
                                          int row0, int k0, uint32_t sdst, int tid)
{
#pragma unroll
    for (int c = tid; c < ROWS * 8; c += 128) {
        int r = c >> 3, col = c & 7;
        const void* src = (const void*)(g + (size_t)(row0 + r) * ld + k0 + col * 8);
        uint32_t dst = sdst + ((uint32_t)r << 7) + ((uint32_t)(col ^ (r & 7)) << 4);
        asm volatile("cp.async.cg.shared.global [%0], [%1], 16;\n" :: "r"(dst), "l"(src));
    }
}

// ---------------------------------------------------------------------------
// fp16 GEMM, templated pass count:
//   TWOPASS: D = (Ahi + Alo) * B   (A split fp16 pair)
//   else:    D = Ahi * B
// mode 0: fp32 output; mode 2: fp16 single output
// causal 0: none; 1: skip tiles above diagonal (scores);
//        3: kEnd=(by+1)*BM + load-balance remap of by (PV)
// 128 threads, warps 2m x 2n, warp tile 32x64; reg-level fragment double-buffer.
// ---------------------------------------------------------------------------
template<bool TWOPASS>
__global__ void __launch_bounds__(128, TWOPASS ? 3 : 4)
gemm2h(const fp16* __restrict__ Ahi, const fp16* __restrict__ Alo,
       const fp16* __restrict__ B,
       int K, int lda, int ldb,
       long long sAz, long long sBz, long long sCz,
       float* __restrict__ Cf, fp16* __restrict__ Ch,
       int ldc, int mode, int causal)
{
    constexpr uint32_t STG   = TWOPASS ? STAGE_T : STAGE_O;
    constexpr uint32_t OFF_AH = 0;
    constexpr uint32_t OFF_AL = A_BYTES;                      // unused if !TWOPASS
    constexpr uint32_t OFF_B  = TWOPASS ? 2*A_BYTES : A_BYTES;

    const int bx = blockIdx.x, z = blockIdx.z;
    int by = blockIdx.y;
    if (causal == 3) {
        const int n = gridDim.y;
        by = (by & 1) ? (n - 1 - (by >> 1)) : (by >> 1);
    }
    const int m0 = by * BM, n0 = bx * BN;
    if (causal == 1 && n0 > m0 + (BM - 1)) return;

    const int kEnd = (causal == 3) ? (by + 1) * BM : K;
    const int nit = kEnd / BK;

    const fp16* Ah = Ahi + (size_t)z * sAz;
    const fp16* Al = TWOPASS ? (Alo + (size_t)z * sAz) : nullptr;
    const fp16* Bp = B   + (size_t)z * sBz;

    extern __shared__ char smem_raw[];
    const uint32_t sbase = (smem_u32(smem_raw) + 1023u) & ~1023u;

    const int tid = threadIdx.x;
    const int wid = tid >> 5, lid = tid & 31;
    const int warp_m = wid >> 1;
    const int warp_n = wid & 1;

    float acc[2][8][4];
#pragma unroll
    for (int i = 0; i < 2; i++)
#pragma unroll
        for (int j = 0; j < 8; j++)
#pragma unroll
            for (int q = 0; q < 4; q++) acc[i][j][q] = 0.0f;

    const int a_row_base = warp_m * 32 + (lid & 15);
    const int a_chalf = lid >> 4;
    const int b_row_base = warp_n * 64 + (lid >> 4) * 8 + (lid & 7);
    const int b_chalf = (lid >> 3) & 1;

    load_tile<BM>(Ah, lda, m0, 0, sbase + OFF_AH, tid);
    if (TWOPASS) load_tile<BM>(Al, lda, m0, 0, sbase + OFF_AL, tid);
    load_tile<BN>(Bp, ldb, n0, 0, sbase + OFF_B, tid);
    CP_COMMIT();

    uint32_t ah[2][2][4], al[2][2][4];
    uint32_t bh[2][4][4];

    for (int it = 0; it < nit; it++) {
        const int p = it & 1;
        if (it + 1 < nit) {
            const uint32_t sb = sbase + (p ^ 1) * STG;
            const int k0 = (it + 1) * BK;
            load_tile<BM>(Ah, lda, m0, k0, sb + OFF_AH, tid);
            if (TWOPASS) load_tile<BM>(Al, lda, m0, k0, sb + OFF_AL, tid);
            load_tile<BN>(Bp, ldb, n0, k0, sb + OFF_B, tid);
            CP_COMMIT();
            CP_WAIT1();
        } else {
            CP_WAIT0();
        }
        __syncthreads();

        const uint32_t sb = sbase + p * STG;

        // preload kk=0 fragments
#pragma unroll
        for (int im = 0; im < 2; im++) {
            const int row = a_row_base + im * 16;
            const uint32_t off = ((uint32_t)row << 7) + ((uint32_t)(a_chalf ^ (row & 7)) << 4);
            ldsm4(ah[0][im], sb + OFF_AH + off);
            if (TWOPASS) ldsm4(al[0][im], sb + OFF_AL + off);
        }
#pragma unroll
        for (int jn = 0; jn < 4; jn++) {
            const int n = b_row_base + jn * 16;
            const uint32_t off = ((uint32_t)n << 7) + ((uint32_t)(b_chalf ^ (n & 7)) << 4);
            ldsm4(bh[0][jn], sb + OFF_B + off);
        }

#pragma unroll
        for (int kk = 0; kk < 4; kk++) {
            const int cur = kk & 1, nxt = cur ^ 1;
            if (kk < 3) {   // prefetch kk+1 fragments during kk's MMAs
#pragma unroll
                for (int im = 0; im < 2; im++) {
                    const int row = a_row_base + im * 16;
                    const int c16 = (kk + 1) * 2 + a_chalf;
                    const uint32_t off = ((uint32_t)row << 7) + ((uint32_t)(c16 ^ (row & 7)) << 4);
                    ldsm4(ah[nxt][im], sb + OFF_AH + off);
                    if (TWOPASS) ldsm4(al[nxt][im], sb + OFF_AL + off);
                }
#pragma unroll
                for (int jn = 0; jn < 4; jn++) {
                    const int n = b_row_base + jn * 16;
                    const int c16 = (kk + 1) * 2 + b_chalf;
                    const uint32_t off = ((uint32_t)n << 7) + ((uint32_t)(c16 ^ (n & 7)) << 4);
                    ldsm4(bh[nxt][jn], sb + OFF_B + off);
                }
            }
#pragma unroll
            for (int jn = 0; jn < 4; jn++) {
#pragma unroll
                for (int im = 0; im < 2; im++) {
#pragma unroll
                    for (int h = 0; h < 2; h++) {
                        float* d = acc[im][jn * 2 + h];
                        mma_f16(d, ah[cur][im], bh[cur][jn] + 2 * h);
                        if (TWOPASS) mma_f16(d, al[cur][im], bh[cur][jn] + 2 * h);
                    }
                }
            }
        }
        __syncthreads();
    }

    // epilogue
    const int tq = lid >> 2;
    const int tr = lid & 3;
    const size_t cbase = (size_t)z * (size_t)sCz;
#pragma unroll
    for (int im = 0; im < 2; im++) {
#pragma unroll
        for (int j = 0; j < 8; j++) {
            const int r0 = m0 + warp_m * 32 + im * 16 + tq;
            const int c0 = n0 + warp_n * 64 + j * 8 + tr * 2;
            const float* d = acc[im][j];
            if (mode == 0) {
                *(float2*)(Cf + cbase + (size_t)r0 * ldc + c0)       = make_float2(d[0], d[1]);
                *(float2*)(Cf + cbase + (size_t)(r0 + 8) * ldc + c0) = make_float2(d[2], d[3]);
            } else {
#pragma unroll
                for (int rr = 0; rr < 2; rr++) {
                    __half2 hv;
                    hv.x = __float2half_rn(d[2 * rr]);
                    hv.y = __float2half_rn(d[2 * rr + 1]);
                    const size_t o = cbase + (size_t)(r0 + 8 * rr) * ldc + c0;
                    *(uint32_t*)(Ch + o) = *(uint32_t*)&hv;
                }
            }
        }
    }
}

// ---------------------------------------------------------------------------
// fp32 -> fp16 (hi, lo) pair, elementwise (4 per thread)
// ---------------------------------------------------------------------------
__global__ void __launch_bounds__(256)
split_f32(const float* __restrict__ x, fp16* __restrict__ hi, fp16* __restrict__ lo, int n4)
{
    int i = blockIdx.x * 256 + threadIdx.x;
    if (i >= n4) return;
    float4 v = ((const float4*)x)[i];
    float f[4] = {v.x, v.y, v.z, v.w};
    fp16 h[4]; fp16 l[4];
#pragma unroll
    for (int j = 0; j < 4; j++) {
        h[j] = __float2half_rn(f[j]);
        l[j] = __float2half_rn(f[j] - __half2float(h[j]));
    }
    ((uint2*)hi)[i] = *(uint2*)h;
    ((uint2*)lo)[i] = *(uint2*)l;
}

// ---------------------------------------------------------------------------
// All three weights: W [DIN x DIN] fp32 -> W^T fp16 pair (z selects matrix)
// ---------------------------------------------------------------------------
__global__ void __launch_bounds__(256)
transpose_split3(const float* __restrict__ W0, const float* __restrict__ W1,
                 const float* __restrict__ W2, fp16* __restrict__ Thi,
                 fp16* __restrict__ Tlo)
{
    const int zz = blockIdx.z;
    const float* W = (zz == 0) ? W0 : (zz == 1) ? W1 : W2;
    const size_t zoff = (size_t)zz * DIN * DIN;

    __shared__ float t[32][33];
    const int bx = blockIdx.x * 32, by = blockIdx.y * 32;
    const int x = threadIdx.x, y = threadIdx.y;
#pragma unroll
    for (int i = 0; i < 32; i += 8)
        t[y + i][x] = W[(size_t)(by + y + i) * DIN + bx + x];
    __syncthreads();
#pragma unroll
    for (int i = 0; i < 32; i += 8) {
        float v = t[x][y + i];
        fp16 h = __float2half_rn(v);
        fp16 l = __float2half_rn(v - __half2float(h));
        Thi[zoff + (size_t)(bx + y + i) * DIN + by + x] = h;
        Tlo[zoff + (size_t)(bx + y + i) * DIN + by + x] = l;
    }
}

// ---------------------------------------------------------------------------
// Softmax over k<=q of scale*S, emit fp16 single P, zero-pad to 64 boundary
// ---------------------------------------------------------------------------
__global__ void __launch_bounds__(256)
softmax_h(const float* __restrict__ S, fp16* __restrict__ P, float scale)
{
    const int row = blockIdx.x;
    const int q = row & (SLEN - 1);
    const float* p = S + (size_t)row * SLEN;
    const int L = q + 1;
    const int t = threadIdx.x;

    float v[8];
    float mx = -INFINITY;
#pragma unroll
    for (int i = 0; i < 8; i++) {
        int idx = t + i * 256;
        v[i] = (idx < L) ? p[idx] * scale : -INFINITY;
        mx = fmaxf(mx, v[i]);
    }

    __shared__ float redm[8];
    __shared__ float reds[8];

#pragma unroll
    for (int o = 16; o; o >>= 1) mx = fmaxf(mx, __shfl_xor_sync(0xFFFFFFFFu, mx, o));
    if ((t & 31) == 0) redm[t >> 5] = mx;
    __syncthreads();
    float m = redm[0];
#pragma unroll
    for (int i = 1; i < 8; i++) m = fmaxf(m, redm[i]);

    float s = 0.0f;
#pragma unroll
    for (int i = 0; i < 8; i++) {
        float e = __expf(v[i] - m);
        v[i] = e;
        s += e;
    }
#pragma unroll
    for (int o = 16; o; o >>= 1) s += __shfl_xor_sync(0xFFFFFFFFu, s, o);
    if ((t & 31) == 0) reds[t >> 5] = s;
    __syncthreads();
    float tot = 0.0f;
#pragma unroll
    for (int i = 0; i < 8; i++) tot += reds[i];
    const float inv = 1.0f / tot;

    fp16* ph = P + (size_t)row * SLEN;
    const int pad = (L + 63) & ~63;
#pragma unroll
    for (int i = 0; i < 8; i++) {
        int idx = t + i * 256;
        if (idx < L)        ph[idx] = __float2half_rn(v[i] * inv);
        else if (idx < pad) ph[idx] = __float2half_rn(0.0f);
    }
}

// ---------------------------------------------------------------------------
extern "C" void kernel_launch(void* const* d_in, const int* in_sizes, int n_in,
                              void* d_out, int out_size)
{
    const float* x  = (const float*)d_in[0];
    const float* Wq = (const float*)d_in[1];
    const float* Wk = (const float*)d_in[2];
    const float* Wv = (const float*)d_in[3];
    float* out = (float*)d_out;
    (void)in_sizes; (void)n_in; (void)out_size;

    cudaFuncSetAttribute(gemm2h<true>,  cudaFuncAttributeMaxDynamicSharedMemorySize, SMEM_T);
    cudaFuncSetAttribute(gemm2h<false>, cudaFuncAttributeMaxDynamicSharedMemorySize, SMEM_O);

    fp16 *Xhi, *Xlo, *WThi, *WTlo, *QK, *VT, *P;
    float *Sp;
    cudaGetSymbolAddress((void**)&Xhi, g_Xhi);
    cudaGetSymbolAddress((void**)&Xlo, g_Xlo);
    cudaGetSymbolAddress((void**)&WThi, g_WThi);
    cudaGetSymbolAddress((void**)&WTlo, g_WTlo);
    cudaGetSymbolAddress((void**)&QK, g_QK);
    cudaGetSymbolAddress((void**)&VT, g_VT);
    cudaGetSymbolAddress((void**)&Sp, g_S);
    cudaGetSymbolAddress((void**)&P, g_P);

    const size_t WSTRIDE = (size_t)DIN * DIN;

    // 1) split x into fp16 pair (hi doubles as the quantized B for V proj)
    split_f32<<<(NTOK * DIN / 4) / 256, 256>>>(x, Xhi, Xlo, NTOK * DIN / 4);

    // 2) transpose + split all three weights into fp16 pairs
    {
        dim3 g(DIN / 32, DIN / 32, 3), b(32, 8);
        transpose_split3<<<g, b>>>(Wq, Wk, Wv, WThi, WTlo);
    }

    // 3) merged QK projection (2-pass): A = X pair, B = [Wq^T;Wk^T] hi -> fp16 single
    {
        dim3 g(2 * DIN / BN, NTOK / BM, 1);   // 16 x 128
        gemm2h<true><<<g, 128, SMEM_T>>>(Xhi, Xlo, WThi,
                                         DIN, DIN, DIN, 0, 0, 0,
                                         nullptr, QK, 2 * DIN, 2, 0);
    }

    // 4) V^T projection (2-pass): A = Wv^T pair, B = X hi -> fp16 single
    {
        dim3 g(NTOK / BN, DIN / BM, 1);   // 64 x 16
        gemm2h<true><<<g, 128, SMEM_T>>>(WThi + 2 * WSTRIDE, WTlo + 2 * WSTRIDE, Xhi,
                                         DIN, DIN, DIN, 0, 0, 0,
                                         nullptr, VT, NTOK, 2, 0);
    }

    // 5) scores (1-pass): A = Q single, B = K single (cols 1024..2047), causal skip
    {
        dim3 g(SLEN / BN, SLEN / BM, BATCH);   // 16 x 32 x 4
        gemm2h<false><<<g, 128, SMEM_O>>>(QK, nullptr, QK + DIN,
                                          DIN, 2 * DIN, 2 * DIN,
                                          (long long)SLEN * 2 * DIN, (long long)SLEN * 2 * DIN,
                                          (long long)SLEN * SLEN,
                                          Sp, nullptr, SLEN, 0, 1);
    }

    // 6) softmax -> fp16 single P
    softmax_h<<<BATCH * SLEN, 256>>>(Sp, P, 0.03125f);

    // 7) PV (1-pass): A = P single, B = V^T single, k-bound + remap
    {
        dim3 g(DIN / BN, SLEN / BM, BATCH);    // 8 x 32 x 4
        gemm2h<false><<<g, 128, SMEM_O>>>(P, nullptr, VT,
                                          SLEN, SLEN, NTOK,
                                          (long long)SLEN * SLEN, (long long)SLEN,
                                          (long long)SLEN * DIN,
                                          out, nullptr, DIN, 0, 3);
    }
}

// round 12
// speedup vs baseline: 2.5006x; 1.2885x over previous
#include <cuda_runtime.h>
#include <cuda_fp16.h>
#include <cstdint>
#include <cstddef>

typedef __half fp16;

#define BATCH 4
#define SLEN  2048
#define DIN   1024
#define NTOK  (BATCH*SLEN)

#define BM 64
#define BN 128
#define BK 64
#define A_BYTES (64*128)            // 8KB
#define B_BYTES (128*128)           // 16KB
#define STAGE (A_BYTES + B_BYTES)   // 24KB/stage, 2 stages -> 48KB + pad
#define OFF_A 0
#define OFF_B A_BYTES
#define SMEM_REQ (1024 + 2*STAGE)

// ---------------- scratch (device globals; no allocs allowed) ----------------
__device__ fp16 g_X[(size_t)NTOK*DIN];        // X fp16
__device__ fp16 g_WT[3][(size_t)DIN*DIN];     // W^T fp16; [0],[1] contiguous = QK merged B
__device__ fp16 g_QK[(size_t)NTOK*2*DIN];     // cols 0..1023=Q, 1024..2047=K
__device__ fp16 g_VT[(size_t)DIN*NTOK];       // V^T: [e][b*S+s]
__device__ float g_S[(size_t)BATCH*SLEN*SLEN];    // raw scores (unscaled)
__device__ fp16 g_P[(size_t)BATCH*SLEN*SLEN];     // softmax weights

// ---------------- helpers ----------------
__device__ __forceinline__ uint32_t smem_u32(const void* p) {
    return (uint32_t)__cvta_generic_to_shared(p);
}
#define CP_COMMIT() asm volatile("cp.async.commit_group;\n" ::: "memory")
#define CP_WAIT1()  asm volatile("cp.async.wait_group 1;\n" ::: "memory")
#define CP_WAIT0()  asm volatile("cp.async.wait_group 0;\n" ::: "memory")

__device__ __forceinline__ void ldsm4(uint32_t* r, uint32_t addr) {
    asm volatile("ldmatrix.sync.aligned.m8n8.x4.shared.b16 {%0,%1,%2,%3}, [%4];"
        : "=r"(r[0]), "=r"(r[1]), "=r"(r[2]), "=r"(r[3]) : "r"(addr));
}
__device__ __forceinline__ void mma_f16(float* d, const uint32_t* a, const uint32_t* b) {
    asm volatile(
        "mma.sync.aligned.m16n8k16.row.col.f32.f16.f16.f32 "
        "{%0,%1,%2,%3}, {%4,%5,%6,%7}, {%8,%9}, {%0,%1,%2,%3};"
        : "+f"(d[0]), "+f"(d[1]), "+f"(d[2]), "+f"(d[3])
        : "r"(a[0]), "r"(a[1]), "r"(a[2]), "r"(a[3]), "r"(b[0]), "r"(b[1]));
}

// cp.async a [ROWS x 64 fp16] tile (128B rows) into swizzled smem; 128 threads
template<int ROWS>
__device__ __forceinline__ void load_tile(const fp16* __restrict__ g, int ld,
                                          int row0, int k0, uint32_t sdst, int tid)
{
#pragma unroll
    for (int c = tid; c < ROWS * 8; c += 128) {
        int r = c >> 3, col = c & 7;
        const void* src = (const void*)(g + (size_t)(row0 + r) * ld + k0 + col * 8);
        uint32_t dst = sdst + ((uint32_t)r << 7) + ((uint32_t)(col ^ (r & 7)) << 4);
        asm volatile("cp.async.cg.shared.global [%0], [%1], 16;\n" :: "r"(dst), "l"(src));
    }
}

// ---------------------------------------------------------------------------
// fp16 1-pass warp-MMA GEMM: D[m][n] = sum_k A[m][k]*B[n][k]
// mode 0: fp32 output; mode 2: fp16 output
// causal 0: none; 1: skip tiles above diagonal (scores);
//        3: kEnd=(by+1)*BM + load-balance remap of by (PV)
// 128 threads, warps 2m x 2n, warp tile 32x64; reg-level fragment double-buffer.
// ---------------------------------------------------------------------------
__global__ void __launch_bounds__(128, 4)
gemm1h(const fp16* __restrict__ A, const fp16* __restrict__ B,
       int K, int lda, int ldb,
       long long sAz, long long sBz, long long sCz,
       float* __restrict__ Cf, fp16* __restrict__ Ch,
       int ldc, int mode, int causal)
{
    const int bx = blockIdx.x, z = blockIdx.z;
    int by = blockIdx.y;
    if (causal == 3) {
        const int n = gridDim.y;
        by = (by & 1) ? (n - 1 - (by >> 1)) : (by >> 1);
    }
    const int m0 = by * BM, n0 = bx * BN;
    if (causal == 1 && n0 > m0 + (BM - 1)) return;

    const int kEnd = (causal == 3) ? (by + 1) * BM : K;
    const int nit = kEnd / BK;

    const fp16* Ap = A + (size_t)z * sAz;
    const fp16* Bp = B + (size_t)z * sBz;

    extern __shared__ char smem_raw[];
    const uint32_t sbase = (smem_u32(smem_raw) + 1023u) & ~1023u;

    const int tid = threadIdx.x;
    const int wid = tid >> 5, lid = tid & 31;
    const int warp_m = wid >> 1;
    const int warp_n = wid & 1;

    float acc[2][8][4];
#pragma unroll
    for (int i = 0; i < 2; i++)
#pragma unroll
        for (int j = 0; j < 8; j++)
#pragma unroll
            for (int q = 0; q < 4; q++) acc[i][j][q] = 0.0f;

    const int a_row_base = warp_m * 32 + (lid & 15);
    const int a_chalf = lid >> 4;
    const int b_row_base = warp_n * 64 + (lid >> 4) * 8 + (lid & 7);
    const int b_chalf = (lid >> 3) & 1;

    load_tile<BM>(Ap, lda, m0, 0, sbase + OFF_A, tid);
    load_tile<BN>(Bp, ldb, n0, 0, sbase + OFF_B, tid);
    CP_COMMIT();

    uint32_t ah[2][2][4];
    uint32_t bh[2][4][4];

    for (int it = 0; it < nit; it++) {
        const int p = it & 1;
        if (it + 1 < nit) {
            const uint32_t sb = sbase + (p ^ 1) * STAGE;
            const int k0 = (it + 1) * BK;
            load_tile<BM>(Ap, lda, m0, k0, sb + OFF_A, tid);
            load_tile<BN>(Bp, ldb, n0, k0, sb + OFF_B, tid);
            CP_COMMIT();
            CP_WAIT1();
        } else {
            CP_WAIT0();
        }
        __syncthreads();

        const uint32_t sb = sbase + p * STAGE;

        // preload kk=0 fragments
#pragma unroll
        for (int im = 0; im < 2; im++) {
            const int row = a_row_base + im * 16;
            const uint32_t off = ((uint32_t)row << 7) + ((uint32_t)(a_chalf ^ (row & 7)) << 4);
            ldsm4(ah[0][im], sb + OFF_A + off);
        }
#pragma unroll
        for (int jn = 0; jn < 4; jn++) {
            const int n = b_row_base + jn * 16;
            const uint32_t off = ((uint32_t)n << 7) + ((uint32_t)(b_chalf ^ (n & 7)) << 4);
            ldsm4(bh[0][jn], sb + OFF_B + off);
        }

#pragma unroll
        for (int kk = 0; kk < 4; kk++) {
            const int cur = kk & 1, nxt = cur ^ 1;
            if (kk < 3) {   // prefetch kk+1 fragments during kk's MMAs
#pragma unroll
                for (int im = 0; im < 2; im++) {
                    const int row = a_row_base + im * 16;
                    const int c16 = (kk + 1) * 2 + a_chalf;
                    const uint32_t off = ((uint32_t)row << 7) + ((uint32_t)(c16 ^ (row & 7)) << 4);
                    ldsm4(ah[nxt][im], sb + OFF_A + off);
                }
#pragma unroll
                for (int jn = 0; jn < 4; jn++) {
                    const int n = b_row_base + jn * 16;
                    const int c16 = (kk + 1) * 2 + b_chalf;
                    const uint32_t off = ((uint32_t)n << 7) + ((uint32_t)(c16 ^ (n & 7)) << 4);
                    ldsm4(bh[nxt][jn], sb + OFF_B + off);
                }
            }
#pragma unroll
            for (int jn = 0; jn < 4; jn++) {
#pragma unroll
                for (int im = 0; im < 2; im++) {
#pragma unroll
                    for (int h = 0; h < 2; h++) {
                        mma_f16(acc[im][jn * 2 + h], ah[cur][im], bh[cur][jn] + 2 * h);
                    }
                }
            }
        }
        __syncthreads();
    }

    // epilogue
    const int tq = lid >> 2;
    const int tr = lid & 3;
    const size_t cbase = (size_t)z * (size_t)sCz;
#pragma unroll
    for (int im = 0; im < 2; im++) {
#pragma unroll
        for (int j = 0; j < 8; j++) {
            const int r0 = m0 + warp_m * 32 + im * 16 + tq;
            const int c0 = n0 + warp_n * 64 + j * 8 + tr * 2;
            const float* d = acc[im][j];
            if (mode == 0) {
                *(float2*)(Cf + cbase + (size_t)r0 * ldc + c0)       = make_float2(d[0], d[1]);
                *(float2*)(Cf + cbase + (size_t)(r0 + 8) * ldc + c0) = make_float2(d[2], d[3]);
            } else {
#pragma unroll
                for (int rr = 0; rr < 2; rr++) {
                    __half2 hv;
                    hv.x = __float2half_rn(d[2 * rr]);
                    hv.y = __float2half_rn(d[2 * rr + 1]);
                    const size_t o = cbase + (size_t)(r0 + 8 * rr) * ldc + c0;
                    *(uint32_t*)(Ch + o) = *(uint32_t*)&hv;
                }
            }
        }
    }
}

// ---------------------------------------------------------------------------
// fp32 -> fp16 convert, elementwise (4 per thread)
// ---------------------------------------------------------------------------
__global__ void __launch_bounds__(256)
convert_h(const float* __restrict__ x, fp16* __restrict__ h16, int n4)
{
    int i = blockIdx.x * 256 + threadIdx.x;
    if (i >= n4) return;
    float4 v = ((const float4*)x)[i];
    fp16 h[4];
    h[0] = __float2half_rn(v.x);
    h[1] = __float2half_rn(v.y);
    h[2] = __float2half_rn(v.z);
    h[3] = __float2half_rn(v.w);
    ((uint2*)h16)[i] = *(uint2*)h;
}

// ---------------------------------------------------------------------------
// All three weights: W [DIN x DIN] fp32 -> W^T fp16 (z selects matrix)
// ---------------------------------------------------------------------------
__global__ void __launch_bounds__(256)
transpose3_h(const float* __restrict__ W0, const float* __restrict__ W1,
             const float* __restrict__ W2, fp16* __restrict__ T)
{
    const int zz = blockIdx.z;
    const float* W = (zz == 0) ? W0 : (zz == 1) ? W1 : W2;
    const size_t zoff = (size_t)zz * DIN * DIN;

    __shared__ float t[32][33];
    const int bx = blockIdx.x * 32, by = blockIdx.y * 32;
    const int x = threadIdx.x, y = threadIdx.y;
#pragma unroll
    for (int i = 0; i < 32; i += 8)
        t[y + i][x] = W[(size_t)(by + y + i) * DIN + bx + x];
    __syncthreads();
#pragma unroll
    for (int i = 0; i < 32; i += 8)
        T[zoff + (size_t)(bx + y + i) * DIN + by + x] = __float2half_rn(t[x][y + i]);
}

// ---------------------------------------------------------------------------
// Softmax over k<=q of scale*S, emit fp16 P, zero-pad to 64 boundary
// ---------------------------------------------------------------------------
__global__ void __launch_bounds__(256)
softmax_h(const float* __restrict__ S, fp16* __restrict__ P, float scale)
{
    const int row = blockIdx.x;
    const int q = row & (SLEN - 1);
    const float* p = S + (size_t)row * SLEN;
    const int L = q + 1;
    const int t = threadIdx.x;

    float v[8];
    float mx = -INFINITY;
#pragma unroll
    for (int i = 0; i < 8; i++) {
        int idx = t + i * 256;
        v[i] = (idx < L) ? p[idx] * scale : -INFINITY;
        mx = fmaxf(mx, v[i]);
    }

    __shared__ float redm[8];
    __shared__ float reds[8];

#pragma unroll
    for (int o = 16; o; o >>= 1) mx = fmaxf(mx, __shfl_xor_sync(0xFFFFFFFFu, mx, o));
    if ((t & 31) == 0) redm[t >> 5] = mx;
    __syncthreads();
    float m = redm[0];
#pragma unroll
    for (int i = 1; i < 8; i++) m = fmaxf(m, redm[i]);

    float s = 0.0f;
#pragma unroll
    for (int i = 0; i < 8; i++) {
        float e = __expf(v[i] - m);
        v[i] = e;
        s += e;
    }
#pragma unroll
    for (int o = 16; o; o >>= 1) s += __shfl_xor_sync(0xFFFFFFFFu, s, o);
    if ((t & 31) == 0) reds[t >> 5] = s;
    __syncthreads();
    float tot = 0.0f;
#pragma unroll
    for (int i = 0; i < 8; i++) tot += reds[i];
    const float inv = 1.0f / tot;

    fp16* ph = P + (size_t)row * SLEN;
    const int pad = (L + 63) & ~63;
#pragma unroll
    for (int i = 0; i < 8; i++) {
        int idx = t + i * 256;
        if (idx < L)        ph[idx] = __float2half_rn(v[i] * inv);
        else if (idx < pad) ph[idx] = __float2half_rn(0.0f);
    }
}

// ---------------------------------------------------------------------------
extern "C" void kernel_launch(void* const* d_in, const int* in_sizes, int n_in,
                              void* d_out, int out_size)
{
    const float* x  = (const float*)d_in[0];
    const float* Wq = (const float*)d_in[1];
    const float* Wk = (const float*)d_in[2];
    const float* Wv = (const float*)d_in[3];
    float* out = (float*)d_out;
    (void)in_sizes; (void)n_in; (void)out_size;

    cudaFuncSetAttribute(gemm1h, cudaFuncAttributeMaxDynamicSharedMemorySize, SMEM_REQ);

    fp16 *X, *WT, *QK, *VT, *P;
    float *Sp;
    cudaGetSymbolAddress((void**)&X, g_X);
    cudaGetSymbolAddress((void**)&WT, g_WT);
    cudaGetSymbolAddress((void**)&QK, g_QK);
    cudaGetSymbolAddress((void**)&VT, g_VT);
    cudaGetSymbolAddress((void**)&Sp, g_S);
    cudaGetSymbolAddress((void**)&P, g_P);

    const size_t WSTRIDE = (size_t)DIN * DIN;

    // 1) convert x -> fp16
    convert_h<<<(NTOK * DIN / 4) / 256, 256>>>(x, X, NTOK * DIN / 4);

    // 2) transpose + convert all three weights -> fp16
    {
        dim3 g(DIN / 32, DIN / 32, 3), b(32, 8);
        transpose3_h<<<g, b>>>(Wq, Wk, Wv, WT);
    }

    // 3) merged QK projection: A = X, B = [Wq^T;Wk^T] -> fp16, ldc=2048
    {
        dim3 g(2 * DIN / BN, NTOK / BM, 1);   // 16 x 128
        gemm1h<<<g, 128, SMEM_REQ>>>(X, WT,
                                     DIN, DIN, DIN, 0, 0, 0,
                                     nullptr, QK, 2 * DIN, 2, 0);
    }

    // 4) V^T projection: A = Wv^T, B = X -> fp16
    {
        dim3 g(NTOK / BN, DIN / BM, 1);   // 64 x 16
        gemm1h<<<g, 128, SMEM_REQ>>>(WT + 2 * WSTRIDE, X,
                                     DIN, DIN, DIN, 0, 0, 0,
                                     nullptr, VT, NTOK, 2, 0);
    }

    // 5) scores: A = Q, B = K (cols 1024..2047), causal skip, fp32 out
    {
        dim3 g(SLEN / BN, SLEN / BM, BATCH);   // 16 x 32 x 4
        gemm1h<<<g, 128, SMEM_REQ>>>(QK, QK + DIN,
                                     DIN, 2 * DIN, 2 * DIN,
                                     (long long)SLEN * 2 * DIN, (long long)SLEN * 2 * DIN,
                                     (long long)SLEN * SLEN,
                                     Sp, nullptr, SLEN, 0, 1);
    }

    // 6) softmax -> fp16 P
    softmax_h<<<BATCH * SLEN, 256>>>(Sp, P, 0.03125f);

    // 7) PV: A = P, B = V^T, k-bound + remap, fp32 out
    {
        dim3 g(DIN / BN, SLEN / BM, BATCH);    // 8 x 32 x 4
        gemm1h<<<g, 128, SMEM_REQ>>>(P, VT,
                                     SLEN, SLEN, NTOK,
                                     (long long)SLEN * SLEN, (long long)SLEN,
                                     (long long)SLEN * DIN,
                                     out, nullptr, DIN, 0, 3);
    }
}

// round 13
// speedup vs baseline: 2.5070x; 1.0026x over previous
#include <cuda_runtime.h>
#include <cuda_fp16.h>
#include <cstdint>
#include <cstddef>

typedef __half fp16;

#define BATCH 4
#define SLEN  2048
#define DIN   1024
#define NTOK  (BATCH*SLEN)

// CTA 128x128x64, 4 warps (2x2), warp tile 64x64, 1-pass fp16, 2 CTAs/SM
#define BM 128
#define BN 128
#define BK 64
#define A_BYTES (128*128)           // 16KB
#define B_BYTES (128*128)           // 16KB
#define STAGE (A_BYTES + B_BYTES)   // 32KB/stage, 2 stages
#define OFF_A 0
#define OFF_B A_BYTES
#define SMEM_REQ (1024 + 2*STAGE)   // ~65KB

// ---------------- scratch (device globals; no allocs allowed) ----------------
__device__ fp16 g_X[(size_t)NTOK*DIN];        // X fp16
__device__ fp16 g_WT[3][(size_t)DIN*DIN];     // W^T fp16; [0],[1] contiguous = QK merged B
__device__ fp16 g_QK[(size_t)NTOK*2*DIN];     // cols 0..1023=Q, 1024..2047=K
__device__ fp16 g_VT[(size_t)DIN*NTOK];       // V^T: [e][b*S+s]
__device__ float g_S[(size_t)BATCH*SLEN*SLEN];    // raw scores (unscaled)
__device__ fp16 g_P[(size_t)BATCH*SLEN*SLEN];     // softmax weights

// ---------------- helpers ----------------
__device__ __forceinline__ uint32_t smem_u32(const void* p) {
    return (uint32_t)__cvta_generic_to_shared(p);
}
#define CP_COMMIT() asm volatile("cp.async.commit_group;\n" ::: "memory")
#define CP_WAIT1()  asm volatile("cp.async.wait_group 1;\n" ::: "memory")
#define CP_WAIT0()  asm volatile("cp.async.wait_group 0;\n" ::: "memory")

__device__ __forceinline__ void ldsm4(uint32_t* r, uint32_t addr) {
    asm volatile("ldmatrix.sync.aligned.m8n8.x4.shared.b16 {%0,%1,%2,%3}, [%4];"
        : "=r"(r[0]), "=r"(r[1]), "=r"(r[2]), "=r"(r[3]) : "r"(addr));
}
__device__ __forceinline__ void mma_f16(float* d, const uint32_t* a, const uint32_t* b) {
    asm volatile(
        "mma.sync.aligned.m16n8k16.row.col.f32.f16.f16.f32 "
        "{%0,%1,%2,%3}, {%4,%5,%6,%7}, {%8,%9}, {%0,%1,%2,%3};"
        : "+f"(d[0]), "+f"(d[1]), "+f"(d[2]), "+f"(d[3])
        : "r"(a[0]), "r"(a[1]), "r"(a[2]), "r"(a[3]), "r"(b[0]), "r"(b[1]));
}

// cp.async a [128 x 64 fp16] tile (128B rows) into swizzled smem; 128 threads
__device__ __forceinline__ void load_tile(const fp16* __restrict__ g, int ld,
                                          int row0, int k0, uint32_t sdst, int tid)
{
#pragma unroll
    for (int c = tid; c < 128 * 8; c += 128) {
        int r = c >> 3, col = c & 7;
        const void* src = (const void*)(g + (size_t)(row0 + r) * ld + k0 + col * 8);
        uint32_t dst = sdst + ((uint32_t)r << 7) + ((uint32_t)(col ^ (r & 7)) << 4);
        asm volatile("cp.async.cg.shared.global [%0], [%1], 16;\n" :: "r"(dst), "l"(src));
    }
}

// ---------------------------------------------------------------------------
// fp16 1-pass warp-MMA GEMM: D[m][n] = sum_k A[m][k]*B[n][k]
// mode 0: fp32 output; mode 2: fp16 output
// causal 0: none; 1: skip tiles above diagonal (scores);
//        3: kEnd=(by+1)*BM + load-balance remap of by (PV)
// 128 threads, warps 2m x 2n, warp tile 64x64; reg-level fragment double-buffer.
// ---------------------------------------------------------------------------
__global__ void __launch_bounds__(128, 2)
gemm1h(const fp16* __restrict__ A, const fp16* __restrict__ B,
       int K, int lda, int ldb,
       long long sAz, long long sBz, long long sCz,
       float* __restrict__ Cf, fp16* __restrict__ Ch,
       int ldc, int mode, int causal)
{
    const int bx = blockIdx.x, z = blockIdx.z;
    int by = blockIdx.y;
    if (causal == 3) {
        const int n = gridDim.y;
        by = (by & 1) ? (n - 1 - (by >> 1)) : (by >> 1);
    }
    const int m0 = by * BM, n0 = bx * BN;
    if (causal == 1 && n0 > m0 + (BM - 1)) return;

    const int kEnd = (causal == 3) ? (by + 1) * BM : K;
    const int nit = kEnd / BK;

    const fp16* Ap = A + (size_t)z * sAz;
    const fp16* Bp = B + (size_t)z * sBz;

    extern __shared__ char smem_raw[];
    const uint32_t sbase = (smem_u32(smem_raw) + 1023u) & ~1023u;

    const int tid = threadIdx.x;
    const int wid = tid >> 5, lid = tid & 31;
    const int warp_m = wid >> 1;        // 0..1 (64 rows each)
    const int warp_n = wid & 1;         // 0..1 (64 cols each)

    float acc[4][8][4];                 // 128 regs
#pragma unroll
    for (int i = 0; i < 4; i++)
#pragma unroll
        for (int j = 0; j < 8; j++)
#pragma unroll
            for (int q = 0; q < 4; q++) acc[i][j][q] = 0.0f;

    const int a_row_base = warp_m * 64 + (lid & 15);
    const int a_chalf = lid >> 4;
    const int b_row_base = warp_n * 64 + (lid >> 4) * 8 + (lid & 7);
    const int b_chalf = (lid >> 3) & 1;

    load_tile(Ap, lda, m0, 0, sbase + OFF_A, tid);
    load_tile(Bp, ldb, n0, 0, sbase + OFF_B, tid);
    CP_COMMIT();

    uint32_t ah[2][4][4];               // [buf][im][4]
    uint32_t bh[2][4][4];               // [buf][jn][4]

    for (int it = 0; it < nit; it++) {
        const int p = it & 1;
        if (it + 1 < nit) {
            const uint32_t sb = sbase + (p ^ 1) * STAGE;
            const int k0 = (it + 1) * BK;
            load_tile(Ap, lda, m0, k0, sb + OFF_A, tid);
            load_tile(Bp, ldb, n0, k0, sb + OFF_B, tid);
            CP_COMMIT();
            CP_WAIT1();
        } else {
            CP_WAIT0();
        }
        __syncthreads();

        const uint32_t sb = sbase + p * STAGE;

        // preload kk=0 fragments into buffer 0
#pragma unroll
        for (int im = 0; im < 4; im++) {
            const int row = a_row_base + im * 16;
            const uint32_t off = ((uint32_t)row << 7) + ((uint32_t)(a_chalf ^ (row & 7)) << 4);
            ldsm4(ah[0][im], sb + OFF_A + off);
        }
#pragma unroll
        for (int jn = 0; jn < 4; jn++) {
            const int n = b_row_base + jn * 16;
            const uint32_t off = ((uint32_t)n << 7) + ((uint32_t)(b_chalf ^ (n & 7)) << 4);
            ldsm4(bh[0][jn], sb + OFF_B + off);
        }

#pragma unroll
        for (int kk = 0; kk < 4; kk++) {
            const int cur = kk & 1, nxt = cur ^ 1;
            if (kk < 3) {   // prefetch kk+1 fragments during kk's MMAs
#pragma unroll
                for (int im = 0; im < 4; im++) {
                    const int row = a_row_base + im * 16;
                    const int c16 = (kk + 1) * 2 + a_chalf;
                    const uint32_t off = ((uint32_t)row << 7) + ((uint32_t)(c16 ^ (row & 7)) << 4);
                    ldsm4(ah[nxt][im], sb + OFF_A + off);
                }
#pragma unroll
                for (int jn = 0; jn < 4; jn++) {
                    const int n = b_row_base + jn * 16;
                    const int c16 = (kk + 1) * 2 + b_chalf;
                    const uint32_t off = ((uint32_t)n << 7) + ((uint32_t)(c16 ^ (n & 7)) << 4);
                    ldsm4(bh[nxt][jn], sb + OFF_B + off);
                }
            }
#pragma unroll
            for (int jn = 0; jn < 4; jn++) {
#pragma unroll
                for (int im = 0; im < 4; im++) {
#pragma unroll
                    for (int h = 0; h < 2; h++) {
                        mma_f16(acc[im][jn * 2 + h], ah[cur][im], bh[cur][jn] + 2 * h);
                    }
                }
            }
        }
        __syncthreads();
    }

    // epilogue
    const int tq = lid >> 2;
    const int tr = lid & 3;
    const size_t cbase = (size_t)z * (size_t)sCz;
#pragma unroll
    for (int im = 0; im < 4; im++) {
#pragma unroll
        for (int j = 0; j < 8; j++) {
            const int r0 = m0 + warp_m * 64 + im * 16 + tq;
            const int c0 = n0 + warp_n * 64 + j * 8 + tr * 2;
            const float* d = acc[im][j];
            if (mode == 0) {
                *(float2*)(Cf + cbase + (size_t)r0 * ldc + c0)       = make_float2(d[0], d[1]);
                *(float2*)(Cf + cbase + (size_t)(r0 + 8) * ldc + c0) = make_float2(d[2], d[3]);
            } else {
#pragma unroll
                for (int rr = 0; rr < 2; rr++) {
                    __half2 hv;
                    hv.x = __float2half_rn(d[2 * rr]);
                    hv.y = __float2half_rn(d[2 * rr + 1]);
                    const size_t o = cbase + (size_t)(r0 + 8 * rr) * ldc + c0;
                    *(uint32_t*)(Ch + o) = *(uint32_t*)&hv;
                }
            }
        }
    }
}

// ---------------------------------------------------------------------------
// fp32 -> fp16 convert, elementwise (4 per thread)
// ---------------------------------------------------------------------------
__global__ void __launch_bounds__(256)
convert_h(const float* __restrict__ x, fp16* __restrict__ h16, int n4)
{
    int i = blockIdx.x * 256 + threadIdx.x;
    if (i >= n4) return;
    float4 v = ((const float4*)x)[i];
    fp16 h[4];
    h[0] = __float2half_rn(v.x);
    h[1] = __float2half_rn(v.y);
    h[2] = __float2half_rn(v.z);
    h[3] = __float2half_rn(v.w);
    ((uint2*)h16)[i] = *(uint2*)h;
}

// ---------------------------------------------------------------------------
// All three weights: W [DIN x DIN] fp32 -> W^T fp16 (z selects matrix)
// ---------------------------------------------------------------------------
__global__ void __launch_bounds__(256)
transpose3_h(const float* __restrict__ W0, const float* __restrict__ W1,
             const float* __restrict__ W2, fp16* __restrict__ T)
{
    const int zz = blockIdx.z;
    const float* W = (zz == 0) ? W0 : (zz == 1) ? W1 : W2;
    const size_t zoff = (size_t)zz * DIN * DIN;

    __shared__ float t[32][33];
    const int bx = blockIdx.x * 32, by = blockIdx.y * 32;
    const int x = threadIdx.x, y = threadIdx.y;
#pragma unroll
    for (int i = 0; i < 32; i += 8)
        t[y + i][x] = W[(size_t)(by + y + i) * DIN + bx + x];
    __syncthreads();
#pragma unroll
    for (int i = 0; i < 32; i += 8)
        T[zoff + (size_t)(bx + y + i) * DIN + by + x] = __float2half_rn(t[x][y + i]);
}

// ---------------------------------------------------------------------------
// Softmax over k<=q of scale*S, emit fp16 P, zero-pad to 128 boundary
// (PV reads whole 128-wide k-tiles, so pad-to-128 is load-bearing)
// ---------------------------------------------------------------------------
__global__ void __launch_bounds__(256)
softmax_h(const float* __restrict__ S, fp16* __restrict__ P, float scale)
{
    const int row = blockIdx.x;
    const int q = row & (SLEN - 1);
    const float* p = S + (size_t)row * SLEN;
    const int L = q + 1;
    const int t = threadIdx.x;

    float v[8];
    float mx = -INFINITY;
#pragma unroll
    for (int i = 0; i < 8; i++) {
        int idx = t + i * 256;
        v[i] = (idx < L) ? p[idx] * scale : -INFINITY;
        mx = fmaxf(mx, v[i]);
    }

    __shared__ float redm[8];
    __shared__ float reds[8];

#pragma unroll
    for (int o = 16; o; o >>= 1) mx = fmaxf(mx, __shfl_xor_sync(0xFFFFFFFFu, mx, o));
    if ((t & 31) == 0) redm[t >> 5] = mx;
    __syncthreads();
    float m = redm[0];
#pragma unroll
    for (int i = 1; i < 8; i++) m = fmaxf(m, redm[i]);

    float s = 0.0f;
#pragma unroll
    for (int i = 0; i < 8; i++) {
        float e = __expf(v[i] - m);
        v[i] = e;
        s += e;
    }
#pragma unroll
    for (int o = 16; o; o >>= 1) s += __shfl_xor_sync(0xFFFFFFFFu, s, o);
    if ((t & 31) == 0) reds[t >> 5] = s;
    __syncthreads();
    float tot = 0.0f;
#pragma unroll
    for (int i = 0; i < 8; i++) tot += reds[i];
    const float inv = 1.0f / tot;

    fp16* ph = P + (size_t)row * SLEN;
    const int pad = (L + 127) & ~127;
#pragma unroll
    for (int i = 0; i < 8; i++) {
        int idx = t + i * 256;
        if (idx < L)        ph[idx] = __float2half_rn(v[i] * inv);
        else if (idx < pad) ph[idx] = __float2half_rn(0.0f);
    }
}

// ---------------------------------------------------------------------------
extern "C" void kernel_launch(void* const* d_in, const int* in_sizes, int n_in,
                              void* d_out, int out_size)
{
    const float* x  = (const float*)d_in[0];
    const float* Wq = (const float*)d_in[1];
    const float* Wk = (const float*)d_in[2];
    const float* Wv = (const float*)d_in[3];
    float* out = (float*)d_out;
    (void)in_sizes; (void)n_in; (void)out_size;

    cudaFuncSetAttribute(gemm1h, cudaFuncAttributeMaxDynamicSharedMemorySize, SMEM_REQ);

    fp16 *X, *WT, *QK, *VT, *P;
    float *Sp;
    cudaGetSymbolAddress((void**)&X, g_X);
    cudaGetSymbolAddress((void**)&WT, g_WT);
    cudaGetSymbolAddress((void**)&QK, g_QK);
    cudaGetSymbolAddress((void**)&VT, g_VT);
    cudaGetSymbolAddress((void**)&Sp, g_S);
    cudaGetSymbolAddress((void**)&P, g_P);

    const size_t WSTRIDE = (size_t)DIN * DIN;

    // 1) convert x -> fp16
    convert_h<<<(NTOK * DIN / 4) / 256, 256>>>(x, X, NTOK * DIN / 4);

    // 2) transpose + convert all three weights -> fp16
    {
        dim3 g(DIN / 32, DIN / 32, 3), b(32, 8);
        transpose3_h<<<g, b>>>(Wq, Wk, Wv, WT);
    }

    // 3) merged QK projection: A = X, B = [Wq^T;Wk^T] -> fp16, ldc=2048
    {
        dim3 g(2 * DIN / BN, NTOK / BM, 1);   // 16 x 64
        gemm1h<<<g, 128, SMEM_REQ>>>(X, WT,
                                     DIN, DIN, DIN, 0, 0, 0,
                                     nullptr, QK, 2 * DIN, 2, 0);
    }

    // 4) V^T projection: A = Wv^T, B = X -> fp16
    {
        dim3 g(NTOK / BN, DIN / BM, 1);   // 64 x 8
        gemm1h<<<g, 128, SMEM_REQ>>>(WT + 2 * WSTRIDE, X,
                                     DIN, DIN, DIN, 0, 0, 0,
                                     nullptr, VT, NTOK, 2, 0);
    }

    // 5) scores: A = Q, B = K (cols 1024..2047), causal skip, fp32 out
    {
        dim3 g(SLEN / BN, SLEN / BM, BATCH);   // 16 x 16 x 4
        gemm1h<<<g, 128, SMEM_REQ>>>(QK, QK + DIN,
                                     DIN, 2 * DIN, 2 * DIN,
                                     (long long)SLEN * 2 * DIN, (long long)SLEN * 2 * DIN,
                                     (long long)SLEN * SLEN,
                                     Sp, nullptr, SLEN, 0, 1);
    }

    // 6) softmax -> fp16 P (pad to 128)
    softmax_h<<<BATCH * SLEN, 256>>>(Sp, P, 0.03125f);

    // 7) PV: A = P, B = V^T, k-bound + remap, fp32 out
    {
        dim3 g(DIN / BN, SLEN / BM, BATCH);    // 8 x 16 x 4
        gemm1h<<<g, 128, SMEM_REQ>>>(P, VT,
                                     SLEN, SLEN, NTOK,
                                     (long long)SLEN * SLEN, (long long)SLEN,
                                     (long long)SLEN * DIN,
                                     out, nullptr, DIN, 0, 3);
    }
}

// round 14
// speedup vs baseline: 2.6015x; 1.0377x over previous
#include <cuda_runtime.h>
#include <cuda_fp16.h>
#include <cstdint>
#include <cstddef>

typedef __half fp16;

#define BATCH 4
#define SLEN  2048
#define DIN   1024
#define NTOK  (BATCH*SLEN)

// CTA 64x128xK128 (two 64-col panels per stage), 4 warps (2x2), warp 32x64
#define BM 64
#define BN 128
#define BK 128
#define A_PANEL (64*128)            // 8KB  (64 rows x 128B)
#define B_PANEL (128*128)           // 16KB (128 rows x 128B)
#define A_BYTES (2*A_PANEL)         // 16KB
#define B_BYTES (2*B_PANEL)         // 32KB
#define OFF_A 0
#define OFF_B A_BYTES
#define STAGE (A_BYTES + B_BYTES)   // 48KB/stage, 2 stages
#define SMEM_REQ (1024 + 2*STAGE)   // ~97KB -> 2 CTAs/SM

// ---------------- scratch (device globals; no allocs allowed) ----------------
__device__ fp16 g_X[(size_t)NTOK*DIN];        // X fp16
__device__ fp16 g_WT[3][(size_t)DIN*DIN];     // W^T fp16; [0],[1] contiguous = QK merged B
__device__ fp16 g_QK[(size_t)NTOK*2*DIN];     // cols 0..1023=Q, 1024..2047=K
__device__ fp16 g_VT[(size_t)DIN*NTOK];       // V^T: [e][b*S+s]
__device__ float g_S[(size_t)BATCH*SLEN*SLEN];    // raw scores (unscaled)
__device__ fp16 g_P[(size_t)BATCH*SLEN*SLEN];     // softmax weights (zero-padded to 128)

// ---------------- helpers ----------------
__device__ __forceinline__ uint32_t smem_u32(const void* p) {
    return (uint32_t)__cvta_generic_to_shared(p);
}
#define CP_COMMIT() asm volatile("cp.async.commit_group;\n" ::: "memory")
#define CP_WAIT1()  asm volatile("cp.async.wait_group 1;\n" ::: "memory")
#define CP_WAIT0()  asm volatile("cp.async.wait_group 0;\n" ::: "memory")

__device__ __forceinline__ void ldsm4(uint32_t* r, uint32_t addr) {
    asm volatile("ldmatrix.sync.aligned.m8n8.x4.shared.b16 {%0,%1,%2,%3}, [%4];"
        : "=r"(r[0]), "=r"(r[1]), "=r"(r[2]), "=r"(r[3]) : "r"(addr));
}
__device__ __forceinline__ void mma_f16(float* d, const uint32_t* a, const uint32_t* b) {
    asm volatile(
        "mma.sync.aligned.m16n8k16.row.col.f32.f16.f16.f32 "
        "{%0,%1,%2,%3}, {%4,%5,%6,%7}, {%8,%9}, {%0,%1,%2,%3};"
        : "+f"(d[0]), "+f"(d[1]), "+f"(d[2]), "+f"(d[3])
        : "r"(a[0]), "r"(a[1]), "r"(a[2]), "r"(a[3]), "r"(b[0]), "r"(b[1]));
}

// cp.async a [ROWS x 64 fp16] panel (128B rows) into swizzled smem; 128 threads
template<int ROWS>
__device__ __forceinline__ void load_panel(const fp16* __restrict__ g, int ld,
                                           int row0, int k0, uint32_t sdst, int tid)
{
#pragma unroll
    for (int c = tid; c < ROWS * 8; c += 128) {
        int r = c >> 3, col = c & 7;
        const void* src = (const void*)(g + (size_t)(row0 + r) * ld + k0 + col * 8);
        uint32_t dst = sdst + ((uint32_t)r << 7) + ((uint32_t)(col ^ (r & 7)) << 4);
        asm volatile("cp.async.cg.shared.global [%0], [%1], 16;\n" :: "r"(dst), "l"(src));
    }
}

// load one full K=128 stage (A 2 panels + B 2 panels)
__device__ __forceinline__ void load_stage(const fp16* A, const fp16* B, int lda, int ldb,
                                           int m0, int n0, int k0, uint32_t sb, int tid)
{
    load_panel<BM>(A, lda, m0, k0,      sb + OFF_A, tid);
    load_panel<BM>(A, lda, m0, k0 + 64, sb + OFF_A + A_PANEL, tid);
    load_panel<BN>(B, ldb, n0, k0,      sb + OFF_B, tid);
    load_panel<BN>(B, ldb, n0, k0 + 64, sb + OFF_B + B_PANEL, tid);
}

// ---------------------------------------------------------------------------
// fp16 1-pass warp-MMA GEMM, K-stage = 128 (8 kk-steps per syncthreads pair)
// mode 0: fp32 output; mode 2: fp16 output
// causal 0: none; 1: skip tiles above diagonal (scores);
//        3: kEnd=(by+1)*BM rounded UP to 128 (P zero-padded) + by remap (PV)
// ---------------------------------------------------------------------------
__global__ void __launch_bounds__(128, 2)
gemm1h(const fp16* __restrict__ A, const fp16* __restrict__ B,
       int K, int lda, int ldb,
       long long sAz, long long sBz, long long sCz,
       float* __restrict__ Cf, fp16* __restrict__ Ch,
       int ldc, int mode, int causal)
{
    const int bx = blockIdx.x, z = blockIdx.z;
    int by = blockIdx.y;
    if (causal == 3) {
        const int n = gridDim.y;
        by = (by & 1) ? (n - 1 - (by >> 1)) : (by >> 1);
    }
    const int m0 = by * BM, n0 = bx * BN;
    if (causal == 1 && n0 > m0 + (BM - 1)) return;

    int nit;
    if (causal == 3) nit = ((by + 1) * BM + BK - 1) / BK;   // round up; P pad = 0
    else             nit = K / BK;

    const fp16* Ap = A + (size_t)z * sAz;
    const fp16* Bp = B + (size_t)z * sBz;

    extern __shared__ char smem_raw[];
    const uint32_t sbase = (smem_u32(smem_raw) + 1023u) & ~1023u;

    const int tid = threadIdx.x;
    const int wid = tid >> 5, lid = tid & 31;
    const int warp_m = wid >> 1;        // 0..1 (32 rows each)
    const int warp_n = wid & 1;         // 0..1 (64 cols each)

    float acc[2][8][4];
#pragma unroll
    for (int i = 0; i < 2; i++)
#pragma unroll
        for (int j = 0; j < 8; j++)
#pragma unroll
            for (int q = 0; q < 4; q++) acc[i][j][q] = 0.0f;

    const int a_row_base = warp_m * 32 + (lid & 15);
    const int a_chalf = lid >> 4;
    const int b_row_base = warp_n * 64 + (lid >> 4) * 8 + (lid & 7);
    const int b_chalf = (lid >> 3) & 1;

    load_stage(Ap, Bp, lda, ldb, m0, n0, 0, sbase, tid);
    CP_COMMIT();

    uint32_t ah[2][2][4];               // [buf][im][4]
    uint32_t bh[2][4][4];               // [buf][jn][4]

    for (int it = 0; it < nit; it++) {
        const int p = it & 1;
        if (it + 1 < nit) {
            load_stage(Ap, Bp, lda, ldb, m0, n0, (it + 1) * BK,
                       sbase + (p ^ 1) * STAGE, tid);
            CP_COMMIT();
            CP_WAIT1();
        } else {
            CP_WAIT0();
        }
        __syncthreads();

        const uint32_t sb = sbase + p * STAGE;

        // preload kk=0 fragments (panel 0)
#pragma unroll
        for (int im = 0; im < 2; im++) {
            const int row = a_row_base + im * 16;
            const uint32_t off = ((uint32_t)row << 7) + ((uint32_t)(a_chalf ^ (row & 7)) << 4);
            ldsm4(ah[0][im], sb + OFF_A + off);
        }
#pragma unroll
        for (int jn = 0; jn < 4; jn++) {
            const int n = b_row_base + jn * 16;
            const uint32_t off = ((uint32_t)n << 7) + ((uint32_t)(b_chalf ^ (n & 7)) << 4);
            ldsm4(bh[0][jn], sb + OFF_B + off);
        }

#pragma unroll
        for (int kk = 0; kk < 8; kk++) {
            const int cur = kk & 1, nxt = cur ^ 1;
            if (kk < 7) {   // prefetch kk+1 fragments during kk's MMAs
                const int kn = kk + 1;
                const uint32_t ap = sb + OFF_A + (uint32_t)(kn >> 2) * A_PANEL;
                const uint32_t bp = sb + OFF_B + (uint32_t)(kn >> 2) * B_PANEL;
                const int kc = (kn & 3) * 2;
#pragma unroll
                for (int im = 0; im < 2; im++) {
                    const int row = a_row_base + im * 16;
                    const int c16 = kc + a_chalf;
                    const uint32_t off = ((uint32_t)row << 7) + ((uint32_t)(c16 ^ (row & 7)) << 4);
                    ldsm4(ah[nxt][im], ap + off);
                }
#pragma unroll
                for (int jn = 0; jn < 4; jn++) {
                    const int n = b_row_base + jn * 16;
                    const int c16 = kc + b_chalf;
                    const uint32_t off = ((uint32_t)n << 7) + ((uint32_t)(c16 ^ (n & 7)) << 4);
                    ldsm4(bh[nxt][jn], bp + off);
                }
            }
#pragma unroll
            for (int jn = 0; jn < 4; jn++) {
#pragma unroll
                for (int im = 0; im < 2; im++) {
#pragma unroll
                    for (int h = 0; h < 2; h++) {
                        mma_f16(acc[im][jn * 2 + h], ah[cur][im], bh[cur][jn] + 2 * h);
                    }
                }
            }
        }
        __syncthreads();
    }

    // epilogue
    const int tq = lid >> 2;
    const int tr = lid & 3;
    const size_t cbase = (size_t)z * (size_t)sCz;
#pragma unroll
    for (int im = 0; im < 2; im++) {
#pragma unroll
        for (int j = 0; j < 8; j++) {
            const int r0 = m0 + warp_m * 32 + im * 16 + tq;
            const int c0 = n0 + warp_n * 64 + j * 8 + tr * 2;
            const float* d = acc[im][j];
            if (mode == 0) {
                *(float2*)(Cf + cbase + (size_t)r0 * ldc + c0)       = make_float2(d[0], d[1]);
                *(float2*)(Cf + cbase + (size_t)(r0 + 8) * ldc + c0) = make_float2(d[2], d[3]);
            } else {
#pragma unroll
                for (int rr = 0; rr < 2; rr++) {
                    __half2 hv;
                    hv.x = __float2half_rn(d[2 * rr]);
                    hv.y = __float2half_rn(d[2 * rr + 1]);
                    const size_t o = cbase + (size_t)(r0 + 8 * rr) * ldc + c0;
                    *(uint32_t*)(Ch + o) = *(uint32_t*)&hv;
                }
            }
        }
    }
}

// ---------------------------------------------------------------------------
// fp32 -> fp16 convert, elementwise (4 per thread)
// ---------------------------------------------------------------------------
__global__ void __launch_bounds__(256)
convert_h(const float* __restrict__ x, fp16* __restrict__ h16, int n4)
{
    int i = blockIdx.x * 256 + threadIdx.x;
    if (i >= n4) return;
    float4 v = ((const float4*)x)[i];
    fp16 h[4];
    h[0] = __float2half_rn(v.x);
    h[1] = __float2half_rn(v.y);
    h[2] = __float2half_rn(v.z);
    h[3] = __float2half_rn(v.w);
    ((uint2*)h16)[i] = *(uint2*)h;
}

// ---------------------------------------------------------------------------
// All three weights: W [DIN x DIN] fp32 -> W^T fp16 (z selects matrix)
// ---------------------------------------------------------------------------
__global__ void __launch_bounds__(256)
transpose3_h(const float* __restrict__ W0, const float* __restrict__ W1,
             const float* __restrict__ W2, fp16* __restrict__ T)
{
    const int zz = blockIdx.z;
    const float* W = (zz == 0) ? W0 : (zz == 1) ? W1 : W2;
    const size_t zoff = (size_t)zz * DIN * DIN;

    __shared__ float t[32][33];
    const int bx = blockIdx.x * 32, by = blockIdx.y * 32;
    const int x = threadIdx.x, y = threadIdx.y;
#pragma unroll
    for (int i = 0; i < 32; i += 8)
        t[y + i][x] = W[(size_t)(by + y + i) * DIN + bx + x];
    __syncthreads();
#pragma unroll
    for (int i = 0; i < 32; i += 8)
        T[zoff + (size_t)(bx + y + i) * DIN + by + x] = __float2half_rn(t[x][y + i]);
}

// ---------------------------------------------------------------------------
// Softmax over k<=q of scale*S, emit fp16 P, zero-pad to 128 boundary
// (PV reads whole 128-wide k-stages, so pad-to-128 is load-bearing)
// ---------------------------------------------------------------------------
__global__ void __launch_bounds__(256)
softmax_h(const float* __restrict__ S, fp16* __restrict__ P, float scale)
{
    const int row = blockIdx.x;
    const int q = row & (SLEN - 1);
    const float* p = S + (size_t)row * SLEN;
    const int L = q + 1;
    const int t = threadIdx.x;

    float v[8];
    float mx = -INFINITY;
#pragma unroll
    for (int i = 0; i < 8; i++) {
        int idx = t + i * 256;
        v[i] = (idx < L) ? p[idx] * scale : -INFINITY;
        mx = fmaxf(mx, v[i]);
    }

    __shared__ float redm[8];
    __shared__ float reds[8];

#pragma unroll
    for (int o = 16; o; o >>= 1) mx = fmaxf(mx, __shfl_xor_sync(0xFFFFFFFFu, mx, o));
    if ((t & 31) == 0) redm[t >> 5] = mx;
    __syncthreads();
    float m = redm[0];
#pragma unroll
    for (int i = 1; i < 8; i++) m = fmaxf(m, redm[i]);

    float s = 0.0f;
#pragma unroll
    for (int i = 0; i < 8; i++) {
        float e = __expf(v[i] - m);
        v[i] = e;
        s += e;
    }
#pragma unroll
    for (int o = 16; o; o >>= 1) s += __shfl_xor_sync(0xFFFFFFFFu, s, o);
    if ((t & 31) == 0) reds[t >> 5] = s;
    __syncthreads();
    float tot = 0.0f;
#pragma unroll
    for (int i = 0; i < 8; i++) tot += reds[i];
    const float inv = 1.0f / tot;

    fp16* ph = P + (size_t)row * SLEN;
    const int pad = (L + 127) & ~127;
#pragma unroll
    for (int i = 0; i < 8; i++) {
        int idx = t + i * 256;
        if (idx < L)        ph[idx] = __float2half_rn(v[i] * inv);
        else if (idx < pad) ph[idx] = __float2half_rn(0.0f);
    }
}

// ---------------------------------------------------------------------------
extern "C" void kernel_launch(void* const* d_in, const int* in_sizes, int n_in,
                              void* d_out, int out_size)
{
    const float* x  = (const float*)d_in[0];
    const float* Wq = (const float*)d_in[1];
    const float* Wk = (const float*)d_in[2];
    const float* Wv = (const float*)d_in[3];
    float* out = (float*)d_out;
    (void)in_sizes; (void)n_in; (void)out_size;

    cudaFuncSetAttribute(gemm1h, cudaFuncAttributeMaxDynamicSharedMemorySize, SMEM_REQ);

    fp16 *X, *WT, *QK, *VT, *P;
    float *Sp;
    cudaGetSymbolAddress((void**)&X, g_X);
    cudaGetSymbolAddress((void**)&WT, g_WT);
    cudaGetSymbolAddress((void**)&QK, g_QK);
    cudaGetSymbolAddress((void**)&VT, g_VT);
    cudaGetSymbolAddress((void**)&Sp, g_S);
    cudaGetSymbolAddress((void**)&P, g_P);

    const size_t WSTRIDE = (size_t)DIN * DIN;

    // 1) convert x -> fp16
    convert_h<<<(NTOK * DIN / 4) / 256, 256>>>(x, X, NTOK * DIN / 4);

    // 2) transpose + convert all three weights -> fp16
    {
        dim3 g(DIN / 32, DIN / 32, 3), b(32, 8);
        transpose3_h<<<g, b>>>(Wq, Wk, Wv, WT);
    }

    // 3) merged QK projection: A = X, B = [Wq^T;Wk^T] -> fp16, ldc=2048
    {
        dim3 g(2 * DIN / BN, NTOK / BM, 1);   // 16 x 128
        gemm1h<<<g, 128, SMEM_REQ>>>(X, WT,
                                     DIN, DIN, DIN, 0, 0, 0,
                                     nullptr, QK, 2 * DIN, 2, 0);
    }

    // 4) V^T projection: A = Wv^T, B = X -> fp16
    {
        dim3 g(NTOK / BN, DIN / BM, 1);   // 64 x 16
        gemm1h<<<g, 128, SMEM_REQ>>>(WT + 2 * WSTRIDE, X,
                                     DIN, DIN, DIN, 0, 0, 0,
                                     nullptr, VT, NTOK, 2, 0);
    }

    // 5) scores: A = Q, B = K (cols 1024..2047), causal skip, fp32 out
    {
        dim3 g(SLEN / BN, SLEN / BM, BATCH);   // 16 x 32 x 4
        gemm1h<<<g, 128, SMEM_REQ>>>(QK, QK + DIN,
                                     DIN, 2 * DIN, 2 * DIN,
                                     (long long)SLEN * 2 * DIN, (long long)SLEN * 2 * DIN,
                                     (long long)SLEN * SLEN,
                                     Sp, nullptr, SLEN, 0, 1);
    }

    // 6) softmax -> fp16 P (pad to 128)
    softmax_h<<<BATCH * SLEN, 256>>>(Sp, P, 0.03125f);

    // 7) PV: A = P, B = V^T, k-bound (rounded to 128) + remap, fp32 out
    {
        dim3 g(DIN / BN, SLEN / BM, BATCH);    // 8 x 32 x 4
        gemm1h<<<g, 128, SMEM_REQ>>>(P, VT,
                                     SLEN, SLEN, NTOK,
                                     (long long)SLEN * SLEN, (long long)SLEN,
                                     (long long)SLEN * DIN,
                                     out, nullptr, DIN, 0, 3);
    }
}